// round 4
// baseline (speedup 1.0000x reference)
#include <cuda_runtime.h>
#include <cuda_bf16.h>
#include <cstdint>

// ---------------------------------------------------------------------------
// APD2Net: graph_conv == 3x3 SAME conv (weights (O,C,9), k=ky*3+kx),
// graph_pool == 2x2 spatial maxpool. Everything stays NCHW.
//
// R4: input tile stored in smem as duplicated (x,x) float2 pairs so the f32x2
// FMA input operand is a single conflict-free LDS.64 (no dup movs). Weights
// stay non-duplicated, read as natural (w_2o,w_2o+1) LDS.64 pairs.
// Per-thread tile: 8 oc x 8 px.
// ---------------------------------------------------------------------------

__device__ float g_bufA[2u * 64u * 384u * 384u];
__device__ float g_bufB[2u * 64u * 384u * 384u];

__device__ __forceinline__ unsigned long long fma2(unsigned long long a,
                                                   unsigned long long b,
                                                   unsigned long long c) {
    unsigned long long d;
    asm("fma.rn.f32x2 %0, %1, %2, %3;" : "=l"(d) : "l"(a), "l"(b), "l"(c));
    return d;
}
__device__ __forceinline__ float2 unpack2(unsigned long long v) {
    float2 r;
    asm("mov.b64 {%0, %1}, %2;" : "=f"(r.x), "=f"(r.y) : "l"(v));
    return r;
}

// weight-row swizzle: group ocg at word woff(ocg); one LDS.64 instruction
// hits 8 distinct bank-pairs -> conflict-free.
__device__ __host__ __forceinline__ int woff_of(int ocg) {
    return ocg * 8 + (ocg >> 2) * 2;
}

// ---------------------------------------------------------------------------
// Tiled conv3x3 + bias + relu. Block: 256 thr = 8 ocg x 32 pg.
// Tile: 64 oc x (TH x TW) px. Thread: 8 oc x 8 px (horizontal).
// ---------------------------------------------------------------------------
template <int CIN, int COUT, int CHUNK, int TH, int TW>
__global__ void __launch_bounds__(256, 2)
conv3x3_bias_relu(const float* __restrict__ in,
                  const float* __restrict__ wgt,
                  const float* __restrict__ bias,
                  float* __restrict__ out,
                  int H, int W)
{
    static_assert(CIN % CHUNK == 0, "CIN divisible by CHUNK");
    static_assert((TH * TW) == 256 && TW % 8 == 0, "tile = 256 px");
    constexpr int OCB = 64;
    constexpr int WROW = 68;            // >= woff_of(7)+8 = 66, even
    constexpr int IROW = TW + 2;        // in float2 pairs
    constexpr int CG = TW / 8;          // col groups

    __shared__ __align__(16) float  wsm[CHUNK][9][WROW];
    __shared__ __align__(16) float2 insm[CHUNK][TH + 2][IROW];   // (x,x) pairs

    const int tiles_x = W / TW;
    const int bx = (blockIdx.x % tiles_x) * TW;
    const int by = (blockIdx.x / tiles_x) * TH;
    const int n  = blockIdx.y;
    const int oc_base = blockIdx.z * OCB;

    const int tid = threadIdx.x;
    const int ocg = tid & 7;
    const int pg  = tid >> 3;           // 0..31
    const int row = pg / CG;            // 0..TH-1
    const int col = (pg % CG) * 8;      // 0,8,...
    const int woff = woff_of(ocg);

    // acc[op][p]: f32x2 lanes = (oc 2op, oc 2op+1) at pixel col+p
    unsigned long long acc[4][8];
    #pragma unroll
    for (int op = 0; op < 4; ++op)
        #pragma unroll
        for (int p = 0; p < 8; ++p) acc[op][p] = 0ull;

    #pragma unroll 1
    for (int c0 = 0; c0 < CIN; c0 += CHUNK) {
        // ---- weights: gmem (contiguous per oc) -> swizzled smem rows
        {
            const float* wg = wgt + (size_t)oc_base * CIN * 9 + (size_t)c0 * 9;
            constexpr int PER_OC = CHUNK * 9;
            constexpr int TOT = OCB * PER_OC;
            for (int idx = tid; idx < TOT; idx += 256) {
                int oc = idx / PER_OC;
                int r  = idx % PER_OC;                    // r = c*9 + k
                float v = wg[(size_t)oc * CIN * 9 + r];
                wsm[r / 9][r % 9][woff_of(oc >> 3) + (oc & 7)] = v;
            }
        }
        // ---- input tile: CHUNK x (TH+2) x (TW+2), zero-padded, duplicated
        {
            constexpr int TILE2D = (TH + 2) * IROW;
            constexpr int TOT = CHUNK * TILE2D;
            for (int idx = tid; idx < TOT; idx += 256) {
                int c   = idx / TILE2D;
                int rem = idx % TILE2D;
                int iy  = rem / IROW;
                int ix  = rem % IROW;
                int gy = by + iy - 1;
                int gx = bx + ix - 1;
                float v = 0.0f;
                if (gy >= 0 && gy < H && gx >= 0 && gx < W)
                    v = in[(((size_t)n * CIN + c0 + c) * H + gy) * W + gx];
                insm[c][iy][ix] = make_float2(v, v);
            }
        }
        __syncthreads();

        // ---- compute
        #pragma unroll 2
        for (int c = 0; c < CHUNK; ++c) {
            #pragma unroll
            for (int ky = 0; ky < 3; ++ky) {
                const unsigned long long* rp =
                    reinterpret_cast<const unsigned long long*>(&insm[c][row + ky][col]);
                unsigned long long d[10];
                #pragma unroll
                for (int i = 0; i < 10; ++i) d[i] = rp[i];
                #pragma unroll
                for (int kx = 0; kx < 3; ++kx) {
                    const float* wp = &wsm[c][ky * 3 + kx][woff];
                    unsigned long long w2[4];
                    #pragma unroll
                    for (int j = 0; j < 4; ++j)
                        w2[j] = *reinterpret_cast<const unsigned long long*>(wp + 2 * j);
                    #pragma unroll
                    for (int op = 0; op < 4; ++op)
                        #pragma unroll
                        for (int p = 0; p < 8; ++p)
                            acc[op][p] = fma2(w2[op], d[kx + p], acc[op][p]);
                }
            }
        }
        __syncthreads();
    }

    // ---- epilogue: bias + relu, float4 stores per oc row
    const int gy = by + row;
    const int gx = bx + col;
    #pragma unroll
    for (int op = 0; op < 4; ++op) {
        const int oc0 = oc_base + ocg * 8 + 2 * op;
        const float b0 = bias[oc0];
        const float b1 = bias[oc0 + 1];
        float lo[8], hi[8];
        #pragma unroll
        for (int p = 0; p < 8; ++p) {
            float2 u = unpack2(acc[op][p]);
            lo[p] = fmaxf(u.x + b0, 0.0f);
            hi[p] = fmaxf(u.y + b1, 0.0f);
        }
        float* dst0 = out + (((size_t)n * COUT + oc0) * H + gy) * W + gx;
        float* dst1 = dst0 + (size_t)H * W;
        *reinterpret_cast<float4*>(dst0)     = make_float4(lo[0], lo[1], lo[2], lo[3]);
        *reinterpret_cast<float4*>(dst0 + 4) = make_float4(lo[4], lo[5], lo[6], lo[7]);
        *reinterpret_cast<float4*>(dst1)     = make_float4(hi[0], hi[1], hi[2], hi[3]);
        *reinterpret_cast<float4*>(dst1 + 4) = make_float4(hi[4], hi[5], hi[6], hi[7]);
    }
}

// ---------------------------------------------------------------------------
// 2x2 maxpool, NCHW.
// ---------------------------------------------------------------------------
__global__ void maxpool2x2(const float* __restrict__ in,
                           float* __restrict__ out,
                           int total, int C, int Ho, int Wo)
{
    int idx = blockIdx.x * blockDim.x + threadIdx.x;
    if (idx >= total) return;
    int x = idx % Wo;
    int y = (idx / Wo) % Ho;
    int rest = idx / (Wo * Ho);
    const int Wi = 2 * Wo;
    const float* p = in + ((size_t)rest * (2 * Ho) + 2 * y) * Wi + 2 * x;
    float m = fmaxf(fmaxf(p[0], p[1]), fmaxf(p[Wi], p[Wi + 1]));
    out[idx] = m;
}

// ---------------------------------------------------------------------------
template <int CIN, int COUT, int CHUNK, int TH, int TW>
static inline void launch_conv(const float* in, const float* w, const float* b,
                               float* out, int H, int W, int N)
{
    dim3 grid((W / TW) * (H / TH), N, COUT / 64);
    conv3x3_bias_relu<CIN, COUT, CHUNK, TH, TW><<<grid, 256>>>(in, w, b, out, H, W);
}

static inline void launch_pool(const float* in, float* out, int N, int C, int Hi, int Wi)
{
    int Ho = Hi / 2, Wo = Wi / 2;
    int total = N * C * Ho * Wo;
    maxpool2x2<<<(total + 255) / 256, 256>>>(in, out, total, C, Ho, Wo);
}

extern "C" void kernel_launch(void* const* d_in, const int* in_sizes, int n_in,
                              void* d_out, int out_size)
{
    (void)in_sizes; (void)n_in; (void)out_size;

    const float* x = (const float*)d_in[0];          // (2,3,384,384)
    const float* w[11];
    const float* b[11];
    for (int k = 1; k <= 10; ++k) {
        w[k] = (const float*)d_in[2 + 2 * (k - 1)];
        b[k] = (const float*)d_in[3 + 2 * (k - 1)];
    }

    float* A;
    float* Bb;
    cudaGetSymbolAddress((void**)&A,  g_bufA);
    cudaGetSymbolAddress((void**)&Bb, g_bufB);
    float* O = (float*)d_out;
    const int N = 2;

    // Stage 1 @ 384x384  (tiles 8x32)
    launch_conv<3,   64, 3, 8, 32>(x,  w[1], b[1], A,  384, 384, N);
    launch_conv<64,  64, 8, 8, 32>(A,  w[2], b[2], Bb, 384, 384, N);
    launch_pool(Bb, A, N, 64, 384, 384);              // -> 192x192

    // Stage 2 @ 192x192
    launch_conv<64, 128, 8, 8, 32>(A,  w[3], b[3], Bb, 192, 192, N);
    launch_conv<128,128, 8, 8, 32>(Bb, w[4], b[4], A,  192, 192, N);
    launch_pool(A, Bb, N, 128, 192, 192);             // -> 96x96

    // Stage 3 @ 96x96
    launch_conv<128,256, 8, 8, 32>(Bb, w[5], b[5], A,  96, 96, N);
    launch_conv<256,256, 8, 8, 32>(A,  w[6], b[6], Bb, 96, 96, N);
    launch_conv<256,256, 8, 8, 32>(Bb, w[7], b[7], A,  96, 96, N);
    launch_pool(A, Bb, N, 256, 96, 96);               // -> 48x48

    // Stage 4 @ 48x48   (tiles 16x16)
    launch_conv<256,512, 8, 16, 16>(Bb, w[8],  b[8],  A,  48, 48, N);
    launch_conv<512,512, 8, 16, 16>(A,  w[9],  b[9],  Bb, 48, 48, N);
    launch_conv<512,512, 8, 16, 16>(Bb, w[10], b[10], O,  48, 48, N);
}

// round 5
// speedup vs baseline: 1.0027x; 1.0027x over previous
#include <cuda_runtime.h>
#include <cuda_bf16.h>
#include <cstdint>

// ---------------------------------------------------------------------------
// APD2Net: graph_conv == 3x3 SAME conv (weights (O,C,9), k=ky*3+kx),
// graph_pool == 2x2 spatial maxpool. Everything stays NCHW.
//
// R5: occupancy rebalance. OC_T=8 x PX_T=4 register tile (32 acc regs) ->
// ~75 regs -> 3 CTAs/SM (24 warps). f32x2 FMA with oc-paired lanes; weights
// via swizzled conflict-free LDS.64; inputs via scalar broadcast LDS + dup.
// ---------------------------------------------------------------------------

__device__ float g_bufA[2u * 64u * 384u * 384u];
__device__ float g_bufB[2u * 64u * 384u * 384u];

__device__ __forceinline__ unsigned long long fma2(unsigned long long a,
                                                   unsigned long long b,
                                                   unsigned long long c) {
    unsigned long long d;
    asm("fma.rn.f32x2 %0, %1, %2, %3;" : "=l"(d) : "l"(a), "l"(b), "l"(c));
    return d;
}
__device__ __forceinline__ unsigned long long dup2(float v) {
    unsigned long long d;
    asm("mov.b64 %0, {%1, %1};" : "=l"(d) : "f"(v));
    return d;
}
__device__ __forceinline__ float2 unpack2(unsigned long long v) {
    float2 r;
    asm("mov.b64 {%0, %1}, %2;" : "=f"(r.x), "=f"(r.y) : "l"(v));
    return r;
}

// weight-row swizzle: 8 oc-groups -> 8 distinct bank pairs for LDS.64
__device__ __host__ __forceinline__ int woff_of(int ocg) {
    return ocg * 8 + (ocg >> 2) * 2;
}

// ---------------------------------------------------------------------------
// Tiled conv3x3 + bias + relu. Block: 256 thr = 8 ocg x 32 pg.
// Tile: 64 oc x (8 x 16) px. Thread: 8 oc x 4 px (horizontal).
// ---------------------------------------------------------------------------
template <int CIN, int COUT, int CHUNK>
__global__ void __launch_bounds__(256, 3)
conv3x3_bias_relu(const float* __restrict__ in,
                  const float* __restrict__ wgt,
                  const float* __restrict__ bias,
                  float* __restrict__ out,
                  int H, int W)
{
    static_assert(CIN % CHUNK == 0, "CIN divisible by CHUNK");
    constexpr int TH = 8;
    constexpr int TW = 16;
    constexpr int OCB = 64;
    constexpr int WROW = 68;            // >= woff_of(7)+8 = 66
    constexpr int IROW = TW + 2;        // 18

    __shared__ __align__(16) float wsm[CHUNK][9][WROW];
    __shared__ float insm[CHUNK][TH + 2][IROW];

    const int tiles_x = W / TW;
    const int bx = (blockIdx.x % tiles_x) * TW;
    const int by = (blockIdx.x / tiles_x) * TH;
    const int n  = blockIdx.y;
    const int oc_base = blockIdx.z * OCB;

    const int tid = threadIdx.x;
    const int ocg = tid & 7;
    const int pg  = tid >> 3;           // 0..31
    const int row = pg >> 2;            // 0..7
    const int col = (pg & 3) * 4;       // 0,4,8,12
    const int woff = woff_of(ocg);

    // acc[op][p]: f32x2 lanes = (oc 2op, oc 2op+1) at pixel col+p
    unsigned long long acc[4][4];
    #pragma unroll
    for (int op = 0; op < 4; ++op)
        #pragma unroll
        for (int p = 0; p < 4; ++p) acc[op][p] = 0ull;

    #pragma unroll 1
    for (int c0 = 0; c0 < CIN; c0 += CHUNK) {
        // ---- weights: gmem (contiguous per oc) -> swizzled smem rows
        {
            const float* wg = wgt + (size_t)oc_base * CIN * 9 + (size_t)c0 * 9;
            constexpr int PER_OC = CHUNK * 9;
            constexpr int TOT = OCB * PER_OC;
            for (int idx = tid; idx < TOT; idx += 256) {
                int oc = idx / PER_OC;
                int r  = idx % PER_OC;                    // r = c*9 + k
                float v = wg[(size_t)oc * CIN * 9 + r];
                wsm[r / 9][r % 9][woff_of(oc >> 3) + (oc & 7)] = v;
            }
        }
        // ---- input tile: CHUNK x (TH+2) x (TW+2), zero-padded borders
        {
            constexpr int TILE2D = (TH + 2) * IROW;
            constexpr int TOT = CHUNK * TILE2D;
            for (int idx = tid; idx < TOT; idx += 256) {
                int c   = idx / TILE2D;
                int rem = idx % TILE2D;
                int iy  = rem / IROW;
                int ix  = rem % IROW;
                int gy = by + iy - 1;
                int gx = bx + ix - 1;
                float v = 0.0f;
                if (gy >= 0 && gy < H && gx >= 0 && gx < W)
                    v = in[(((size_t)n * CIN + c0 + c) * H + gy) * W + gx];
                insm[c][iy][ix] = v;
            }
        }
        __syncthreads();

        // ---- compute
        #pragma unroll 2
        for (int c = 0; c < CHUNK; ++c) {
            #pragma unroll
            for (int ky = 0; ky < 3; ++ky) {
                const float* rp = &insm[c][row + ky][col];
                unsigned long long d[6];
                #pragma unroll
                for (int i = 0; i < 6; ++i) d[i] = dup2(rp[i]);
                #pragma unroll
                for (int kx = 0; kx < 3; ++kx) {
                    const float* wp = &wsm[c][ky * 3 + kx][woff];
                    unsigned long long w2[4];
                    #pragma unroll
                    for (int j = 0; j < 4; ++j)
                        w2[j] = *reinterpret_cast<const unsigned long long*>(wp + 2 * j);
                    #pragma unroll
                    for (int op = 0; op < 4; ++op)
                        #pragma unroll
                        for (int p = 0; p < 4; ++p)
                            acc[op][p] = fma2(w2[op], d[kx + p], acc[op][p]);
                }
            }
        }
        __syncthreads();
    }

    // ---- epilogue: bias + relu, float4 stores per oc row
    const int gy = by + row;
    const int gx = bx + col;
    #pragma unroll
    for (int op = 0; op < 4; ++op) {
        const int oc0 = oc_base + ocg * 8 + 2 * op;
        const float b0 = bias[oc0];
        const float b1 = bias[oc0 + 1];
        float lo[4], hi[4];
        #pragma unroll
        for (int p = 0; p < 4; ++p) {
            float2 u = unpack2(acc[op][p]);
            lo[p] = fmaxf(u.x + b0, 0.0f);
            hi[p] = fmaxf(u.y + b1, 0.0f);
        }
        float* dst0 = out + (((size_t)n * COUT + oc0) * H + gy) * W + gx;
        float* dst1 = dst0 + (size_t)H * W;
        *reinterpret_cast<float4*>(dst0) = make_float4(lo[0], lo[1], lo[2], lo[3]);
        *reinterpret_cast<float4*>(dst1) = make_float4(hi[0], hi[1], hi[2], hi[3]);
    }
}

// ---------------------------------------------------------------------------
// 2x2 maxpool, NCHW.
// ---------------------------------------------------------------------------
__global__ void maxpool2x2(const float* __restrict__ in,
                           float* __restrict__ out,
                           int total, int C, int Ho, int Wo)
{
    int idx = blockIdx.x * blockDim.x + threadIdx.x;
    if (idx >= total) return;
    int x = idx % Wo;
    int y = (idx / Wo) % Ho;
    int rest = idx / (Wo * Ho);
    const int Wi = 2 * Wo;
    const float* p = in + ((size_t)rest * (2 * Ho) + 2 * y) * Wi + 2 * x;
    float m = fmaxf(fmaxf(p[0], p[1]), fmaxf(p[Wi], p[Wi + 1]));
    out[idx] = m;
}

// ---------------------------------------------------------------------------
template <int CIN, int COUT, int CHUNK>
static inline void launch_conv(const float* in, const float* w, const float* b,
                               float* out, int H, int W, int N)
{
    dim3 grid((W / 16) * (H / 8), N, COUT / 64);
    conv3x3_bias_relu<CIN, COUT, CHUNK><<<grid, 256>>>(in, w, b, out, H, W);
}

static inline void launch_pool(const float* in, float* out, int N, int C, int Hi, int Wi)
{
    int Ho = Hi / 2, Wo = Wi / 2;
    int total = N * C * Ho * Wo;
    maxpool2x2<<<(total + 255) / 256, 256>>>(in, out, total, C, Ho, Wo);
}

extern "C" void kernel_launch(void* const* d_in, const int* in_sizes, int n_in,
                              void* d_out, int out_size)
{
    (void)in_sizes; (void)n_in; (void)out_size;

    const float* x = (const float*)d_in[0];          // (2,3,384,384)
    const float* w[11];
    const float* b[11];
    for (int k = 1; k <= 10; ++k) {
        w[k] = (const float*)d_in[2 + 2 * (k - 1)];
        b[k] = (const float*)d_in[3 + 2 * (k - 1)];
    }

    float* A;
    float* Bb;
    cudaGetSymbolAddress((void**)&A,  g_bufA);
    cudaGetSymbolAddress((void**)&Bb, g_bufB);
    float* O = (float*)d_out;
    const int N = 2;

    // Stage 1 @ 384x384
    launch_conv<3,   64, 3>(x,  w[1], b[1], A,  384, 384, N);
    launch_conv<64,  64, 8>(A,  w[2], b[2], Bb, 384, 384, N);
    launch_pool(Bb, A, N, 64, 384, 384);              // -> 192x192

    // Stage 2 @ 192x192
    launch_conv<64, 128, 8>(A,  w[3], b[3], Bb, 192, 192, N);
    launch_conv<128,128, 8>(Bb, w[4], b[4], A,  192, 192, N);
    launch_pool(A, Bb, N, 128, 192, 192);             // -> 96x96

    // Stage 3 @ 96x96
    launch_conv<128,256, 8>(Bb, w[5], b[5], A,  96, 96, N);
    launch_conv<256,256, 8>(A,  w[6], b[6], Bb, 96, 96, N);
    launch_conv<256,256, 8>(Bb, w[7], b[7], A,  96, 96, N);
    launch_pool(A, Bb, N, 256, 96, 96);               // -> 48x48

    // Stage 4 @ 48x48
    launch_conv<256,512, 8>(Bb, w[8],  b[8],  A,  48, 48, N);
    launch_conv<512,512, 8>(A,  w[9],  b[9],  Bb, 48, 48, N);
    launch_conv<512,512, 8>(Bb, w[10], b[10], O,  48, 48, N);
}

// round 7
// speedup vs baseline: 1.0869x; 1.0839x over previous
#include <cuda_runtime.h>
#include <cuda_bf16.h>
#include <cstdint>

// ---------------------------------------------------------------------------
// APD2Net: graph_conv == 3x3 SAME conv (weights (O,C,9), k=ky*3+kx),
// graph_pool == 2x2 spatial maxpool. Everything stays NCHW.
//
// R7 = R6 with the weight-loader truncation bug fixed (CHUNK=3 layer lost
// its last 96 weights to integer division). OCB=32, 128-thread blocks,
// 8 oc x 8 px per thread, f32x2 FMA, LDS.128 weight quads.
// ---------------------------------------------------------------------------

__device__ float g_bufA[2u * 64u * 384u * 384u];
__device__ float g_bufB[2u * 64u * 384u * 384u];

__device__ __forceinline__ unsigned long long fma2(unsigned long long a,
                                                   unsigned long long b,
                                                   unsigned long long c) {
    unsigned long long d;
    asm("fma.rn.f32x2 %0, %1, %2, %3;" : "=l"(d) : "l"(a), "l"(b), "l"(c));
    return d;
}
__device__ __forceinline__ unsigned long long dup2(float v) {
    unsigned long long d;
    asm("mov.b64 %0, {%1, %1};" : "=l"(d) : "f"(v));
    return d;
}
__device__ __forceinline__ float2 unpack2(unsigned long long v) {
    float2 r;
    asm("mov.b64 {%0, %1}, %2;" : "=f"(r.x), "=f"(r.y) : "l"(v));
    return r;
}

// ---------------------------------------------------------------------------
// Tiled conv3x3 + bias + relu. Block: 128 thr = 4 ocg x 32 pg.
// Tile: 32 oc x (TH x TW) px, TH*TW = 256. Thread: 8 oc x 8 px (horizontal).
// ---------------------------------------------------------------------------
template <int CIN, int COUT, int CHUNK, int TH, int TW>
__global__ void __launch_bounds__(128, 4)
conv3x3_bias_relu(const float* __restrict__ in,
                  const float* __restrict__ wgt,
                  const float* __restrict__ bias,
                  float* __restrict__ out,
                  int H, int W)
{
    static_assert(CIN % CHUNK == 0, "CIN divisible by CHUNK");
    static_assert((TH * TW) == 256 && TW % 8 == 0, "tile = 256 px");
    constexpr int OCB = 32;
    constexpr int WROW = 36;            // 32 oc + pad
    constexpr int IROW = TW + 2;
    constexpr int CG = TW / 8;          // col groups

    __shared__ __align__(16) float wsm[CHUNK][9][WROW];
    __shared__ float insm[CHUNK][TH + 2][IROW];

    const int tiles_x = W / TW;
    const int bx = (blockIdx.x % tiles_x) * TW;
    const int by = (blockIdx.x / tiles_x) * TH;
    const int n  = blockIdx.y;
    const int oc_base = blockIdx.z * OCB;

    const int tid = threadIdx.x;
    const int ocg = tid & 3;            // 4 oc groups of 8
    const int pg  = tid >> 2;           // 0..31
    const int row = pg / CG;
    const int col = (pg % CG) * 8;

    // acc[op][p]: f32x2 lanes = (oc 2op, oc 2op+1) at pixel col+p
    unsigned long long acc[4][8];
    #pragma unroll
    for (int op = 0; op < 4; ++op)
        #pragma unroll
        for (int p = 0; p < 8; ++p) acc[op][p] = 0ull;

    #pragma unroll 1
    for (int c0 = 0; c0 < CIN; c0 += CHUNK) {
        // ---- weights: gmem (contiguous per oc) -> smem rows [c][k][oc]
        {
            const float* wg = wgt + (size_t)oc_base * CIN * 9 + (size_t)c0 * 9;
            constexpr int PER_OC = CHUNK * 9;
            constexpr int TOT = OCB * PER_OC;        // 864 (CHUNK=3) / 2304 (CHUNK=8)
            #pragma unroll
            for (int it = 0; it < (TOT + 127) / 128; ++it) {
                int idx = it * 128 + tid;
                if (TOT % 128 == 0 || idx < TOT) {
                    int oc = idx / PER_OC;
                    int r  = idx % PER_OC;               // r = c*9 + k
                    float v = wg[(size_t)oc * CIN * 9 + r];
                    wsm[r / 9][r % 9][oc] = v;
                }
            }
        }
        // ---- input tile: CHUNK x (TH+2) x (TW+2), zero-padded borders
        {
            constexpr int TILE2D = (TH + 2) * IROW;
            constexpr int TOT = CHUNK * TILE2D;
            #pragma unroll 4
            for (int idx = tid; idx < TOT; idx += 128) {
                int c   = idx / TILE2D;
                int rem = idx % TILE2D;
                int iy  = rem / IROW;
                int ix  = rem % IROW;
                int gy = by + iy - 1;
                int gx = bx + ix - 1;
                float v = 0.0f;
                if (gy >= 0 && gy < H && gx >= 0 && gx < W)
                    v = in[(((size_t)n * CIN + c0 + c) * H + gy) * W + gx];
                insm[c][iy][ix] = v;
            }
        }
        __syncthreads();

        // ---- compute
        #pragma unroll 1
        for (int c = 0; c < CHUNK; ++c) {
            #pragma unroll
            for (int ky = 0; ky < 3; ++ky) {
                const float* rp = &insm[c][row + ky][col];
                unsigned long long d[10];
                #pragma unroll
                for (int i = 0; i < 10; ++i) d[i] = dup2(rp[i]);
                #pragma unroll
                for (int kx = 0; kx < 3; ++kx) {
                    const float* wp = &wsm[c][ky * 3 + kx][ocg * 8];
                    ulonglong2 q0 = *reinterpret_cast<const ulonglong2*>(wp);
                    ulonglong2 q1 = *reinterpret_cast<const ulonglong2*>(wp + 4);
                    unsigned long long w2[4] = {q0.x, q0.y, q1.x, q1.y};
                    #pragma unroll
                    for (int op = 0; op < 4; ++op)
                        #pragma unroll
                        for (int p = 0; p < 8; ++p)
                            acc[op][p] = fma2(w2[op], d[kx + p], acc[op][p]);
                }
            }
        }
        __syncthreads();
    }

    // ---- epilogue: bias + relu, float4 stores per oc row
    const int gy = by + row;
    const int gx = bx + col;
    #pragma unroll
    for (int op = 0; op < 4; ++op) {
        const int oc0 = oc_base + ocg * 8 + 2 * op;
        const float b0 = bias[oc0];
        const float b1 = bias[oc0 + 1];
        float lo[8], hi[8];
        #pragma unroll
        for (int p = 0; p < 8; ++p) {
            float2 u = unpack2(acc[op][p]);
            lo[p] = fmaxf(u.x + b0, 0.0f);
            hi[p] = fmaxf(u.y + b1, 0.0f);
        }
        float* dst0 = out + (((size_t)n * COUT + oc0) * H + gy) * W + gx;
        float* dst1 = dst0 + (size_t)H * W;
        *reinterpret_cast<float4*>(dst0)     = make_float4(lo[0], lo[1], lo[2], lo[3]);
        *reinterpret_cast<float4*>(dst0 + 4) = make_float4(lo[4], lo[5], lo[6], lo[7]);
        *reinterpret_cast<float4*>(dst1)     = make_float4(hi[0], hi[1], hi[2], hi[3]);
        *reinterpret_cast<float4*>(dst1 + 4) = make_float4(hi[4], hi[5], hi[6], hi[7]);
    }
}

// ---------------------------------------------------------------------------
// 2x2 maxpool, NCHW.
// ---------------------------------------------------------------------------
__global__ void maxpool2x2(const float* __restrict__ in,
                           float* __restrict__ out,
                           int total, int C, int Ho, int Wo)
{
    int idx = blockIdx.x * blockDim.x + threadIdx.x;
    if (idx >= total) return;
    int x = idx % Wo;
    int y = (idx / Wo) % Ho;
    int rest = idx / (Wo * Ho);
    const int Wi = 2 * Wo;
    const float* p = in + ((size_t)rest * (2 * Ho) + 2 * y) * Wi + 2 * x;
    float m = fmaxf(fmaxf(p[0], p[1]), fmaxf(p[Wi], p[Wi + 1]));
    out[idx] = m;
}

// ---------------------------------------------------------------------------
template <int CIN, int COUT, int CHUNK, int TH, int TW>
static inline void launch_conv(const float* in, const float* w, const float* b,
                               float* out, int H, int W, int N)
{
    dim3 grid((W / TW) * (H / TH), N, COUT / 32);
    conv3x3_bias_relu<CIN, COUT, CHUNK, TH, TW><<<grid, 128>>>(in, w, b, out, H, W);
}

static inline void launch_pool(const float* in, float* out, int N, int C, int Hi, int Wi)
{
    int Ho = Hi / 2, Wo = Wi / 2;
    int total = N * C * Ho * Wo;
    maxpool2x2<<<(total + 255) / 256, 256>>>(in, out, total, C, Ho, Wo);
}

extern "C" void kernel_launch(void* const* d_in, const int* in_sizes, int n_in,
                              void* d_out, int out_size)
{
    (void)in_sizes; (void)n_in; (void)out_size;

    const float* x = (const float*)d_in[0];          // (2,3,384,384)
    const float* w[11];
    const float* b[11];
    for (int k = 1; k <= 10; ++k) {
        w[k] = (const float*)d_in[2 + 2 * (k - 1)];
        b[k] = (const float*)d_in[3 + 2 * (k - 1)];
    }

    float* A;
    float* Bb;
    cudaGetSymbolAddress((void**)&A,  g_bufA);
    cudaGetSymbolAddress((void**)&Bb, g_bufB);
    float* O = (float*)d_out;
    const int N = 2;

    // Stage 1 @ 384x384  (tiles 8x32)
    launch_conv<3,   64, 3, 8, 32>(x,  w[1], b[1], A,  384, 384, N);
    launch_conv<64,  64, 8, 8, 32>(A,  w[2], b[2], Bb, 384, 384, N);
    launch_pool(Bb, A, N, 64, 384, 384);              // -> 192x192

    // Stage 2 @ 192x192
    launch_conv<64, 128, 8, 8, 32>(A,  w[3], b[3], Bb, 192, 192, N);
    launch_conv<128,128, 8, 8, 32>(Bb, w[4], b[4], A,  192, 192, N);
    launch_pool(A, Bb, N, 128, 192, 192);             // -> 96x96

    // Stage 3 @ 96x96
    launch_conv<128,256, 8, 8, 32>(Bb, w[5], b[5], A,  96, 96, N);
    launch_conv<256,256, 8, 8, 32>(A,  w[6], b[6], Bb, 96, 96, N);
    launch_conv<256,256, 8, 8, 32>(Bb, w[7], b[7], A,  96, 96, N);
    launch_pool(A, Bb, N, 256, 96, 96);               // -> 48x48

    // Stage 4 @ 48x48   (tiles 16x16)
    launch_conv<256,512, 8, 16, 16>(Bb, w[8],  b[8],  A,  48, 48, N);
    launch_conv<512,512, 8, 16, 16>(A,  w[9],  b[9],  Bb, 48, 48, N);
    launch_conv<512,512, 8, 16, 16>(Bb, w[10], b[10], O,  48, 48, N);
}

// round 8
// speedup vs baseline: 1.0968x; 1.0091x over previous
#include <cuda_runtime.h>
#include <cuda_bf16.h>
#include <cstdint>

// ---------------------------------------------------------------------------
// APD2Net: graph_conv == 3x3 SAME conv (weights (O,C,9), k=ky*3+kx),
// graph_pool == 2x2 spatial maxpool. Everything stays NCHW.
//
// R8: R3 inner loop (8 oc x 8 px / thread, f32x2 FMA, swizzled LDS.64 weight
// pairs, scalar-broadcast inputs) + cp.async DOUBLE BUFFERING so global loads
// of chunk i+1 overlap compute of chunk i. CHUNK=4 (30.5 KB smem, 2 CTA/SM).
// Stage 4 (512ch @48^2) uses 128-thread blocks / 8x16 tiles -> 288 CTAs.
// ---------------------------------------------------------------------------

__device__ float g_bufA[2u * 64u * 384u * 384u];
__device__ float g_bufB[2u * 64u * 384u * 384u];

__device__ __forceinline__ unsigned long long fma2(unsigned long long a,
                                                   unsigned long long b,
                                                   unsigned long long c) {
    unsigned long long d;
    asm("fma.rn.f32x2 %0, %1, %2, %3;" : "=l"(d) : "l"(a), "l"(b), "l"(c));
    return d;
}
__device__ __forceinline__ unsigned long long dup2(float v) {
    unsigned long long d;
    asm("mov.b64 %0, {%1, %1};" : "=l"(d) : "f"(v));
    return d;
}
__device__ __forceinline__ float2 unpack2(unsigned long long v) {
    float2 r;
    asm("mov.b64 {%0, %1}, %2;" : "=f"(r.x), "=f"(r.y) : "l"(v));
    return r;
}
__device__ __forceinline__ void cp_async4(void* smem_dst, const void* gptr, int src_bytes) {
    unsigned sa = (unsigned)__cvta_generic_to_shared(smem_dst);
    asm volatile("cp.async.ca.shared.global [%0], [%1], 4, %2;\n"
                 :: "r"(sa), "l"(gptr), "r"(src_bytes));
}
__device__ __forceinline__ void cp_commit() { asm volatile("cp.async.commit_group;"); }
__device__ __forceinline__ void cp_wait0()  { asm volatile("cp.async.wait_group 0;"); }

// weight-row swizzle: 8 oc-groups -> 8 distinct bank pairs for LDS.64
__device__ __host__ __forceinline__ int woff_of(int ocg) {
    return ocg * 8 + (ocg >> 2) * 2;
}

// ---------------------------------------------------------------------------
// Tiled conv3x3 + bias + relu, cp.async double-buffered.
// Block: TPB thr = 8 ocg x (TPB/8) pg. Tile: 64 oc x (TH x TW) px.
// Thread: 8 oc x 8 px (horizontal). TH*TW == TPB.
// ---------------------------------------------------------------------------
template <int CIN, int COUT, int CHUNK, int TH, int TW, int TPB>
__global__ void __launch_bounds__(TPB, 512 / TPB)
conv3x3_bias_relu(const float* __restrict__ in,
                  const float* __restrict__ wgt,
                  const float* __restrict__ bias,
                  float* __restrict__ out,
                  int H, int W)
{
    static_assert(CIN % CHUNK == 0, "CIN divisible by CHUNK");
    static_assert(TH * TW == TPB && TW % 8 == 0, "tile px == threads");
    constexpr int OCB = 64;
    constexpr int WROW = 68;            // >= woff_of(7)+8 = 66
    constexpr int IROW = TW + 2;
    constexpr int CG = TW / 8;          // col groups
    constexpr int NCH = CIN / CHUNK;    // number of chunks

    __shared__ __align__(16) float wsm[2][CHUNK][9][WROW];
    __shared__ float insm[2][CHUNK][TH + 2][IROW];

    const int tiles_x = W / TW;
    const int bx = (blockIdx.x % tiles_x) * TW;
    const int by = (blockIdx.x / tiles_x) * TH;
    const int n  = blockIdx.y;
    const int oc_base = blockIdx.z * OCB;

    const int tid = threadIdx.x;
    const int ocg = tid & 7;
    const int pg  = tid >> 3;
    const int row = pg / CG;
    const int col = (pg % CG) * 8;
    const int woff = woff_of(ocg);

    const float* wg_base = wgt + (size_t)oc_base * CIN * 9;

    // ---- async loader for one chunk into stage s
    auto load_chunk = [&](int s, int c0) {
        // weights: OCB oc x CHUNK cin x 9 taps
        {
            constexpr int PER_OC = CHUNK * 9;
            constexpr int TOT = OCB * PER_OC;
            const float* wg = wg_base + (size_t)c0 * 9;
            for (int idx = tid; idx < TOT; idx += TPB) {
                int oc = idx / PER_OC;
                int r  = idx % PER_OC;                 // r = c*9 + k
                cp_async4(&wsm[s][r / 9][r % 9][woff_of(oc >> 3) + (oc & 7)],
                          wg + (size_t)oc * CIN * 9 + r, 4);
            }
        }
        // inputs: CHUNK x (TH+2) x (TW+2), zero-fill borders via src_size=0
        {
            constexpr int TILE2D = (TH + 2) * IROW;
            constexpr int TOT = CHUNK * TILE2D;
            for (int idx = tid; idx < TOT; idx += TPB) {
                int c   = idx / TILE2D;
                int rem = idx % TILE2D;
                int iy  = rem / IROW;
                int ix  = rem % IROW;
                int gy = by + iy - 1;
                int gx = bx + ix - 1;
                bool ok = (gy >= 0 && gy < H && gx >= 0 && gx < W);
                const float* src = ok
                    ? in + (((size_t)n * CIN + c0 + c) * H + gy) * W + gx
                    : in;
                cp_async4(&insm[s][c][iy][ix], src, ok ? 4 : 0);
            }
        }
        cp_commit();
    };

    // acc[op][p]: f32x2 lanes = (oc 2op, oc 2op+1) at pixel col+p
    unsigned long long acc[4][8];
    #pragma unroll
    for (int op = 0; op < 4; ++op)
        #pragma unroll
        for (int p = 0; p < 8; ++p) acc[op][p] = 0ull;

    load_chunk(0, 0);

    #pragma unroll 1
    for (int i = 0; i < NCH; ++i) {
        const int s = i & 1;
        cp_wait0();
        __syncthreads();
        if (i + 1 < NCH) load_chunk(s ^ 1, (i + 1) * CHUNK);

        // ---- compute chunk i from stage s
        #pragma unroll
        for (int c = 0; c < CHUNK; ++c) {
            #pragma unroll
            for (int ky = 0; ky < 3; ++ky) {
                const float* rp = &insm[s][c][row + ky][col];
                unsigned long long d[10];
                #pragma unroll
                for (int j = 0; j < 10; ++j) d[j] = dup2(rp[j]);
                #pragma unroll
                for (int kx = 0; kx < 3; ++kx) {
                    const float* wp = &wsm[s][c][ky * 3 + kx][woff];
                    unsigned long long w2[4];
                    #pragma unroll
                    for (int j = 0; j < 4; ++j)
                        w2[j] = *reinterpret_cast<const unsigned long long*>(wp + 2 * j);
                    #pragma unroll
                    for (int op = 0; op < 4; ++op)
                        #pragma unroll
                        for (int p = 0; p < 8; ++p)
                            acc[op][p] = fma2(w2[op], d[kx + p], acc[op][p]);
                }
            }
        }
        __syncthreads();
    }

    // ---- epilogue: bias + relu, float4 stores per oc row
    const int gy = by + row;
    const int gx = bx + col;
    #pragma unroll
    for (int op = 0; op < 4; ++op) {
        const int oc0 = oc_base + ocg * 8 + 2 * op;
        const float b0 = bias[oc0];
        const float b1 = bias[oc0 + 1];
        float lo[8], hi[8];
        #pragma unroll
        for (int p = 0; p < 8; ++p) {
            float2 u = unpack2(acc[op][p]);
            lo[p] = fmaxf(u.x + b0, 0.0f);
            hi[p] = fmaxf(u.y + b1, 0.0f);
        }
        float* dst0 = out + (((size_t)n * COUT + oc0) * H + gy) * W + gx;
        float* dst1 = dst0 + (size_t)H * W;
        *reinterpret_cast<float4*>(dst0)     = make_float4(lo[0], lo[1], lo[2], lo[3]);
        *reinterpret_cast<float4*>(dst0 + 4) = make_float4(lo[4], lo[5], lo[6], lo[7]);
        *reinterpret_cast<float4*>(dst1)     = make_float4(hi[0], hi[1], hi[2], hi[3]);
        *reinterpret_cast<float4*>(dst1 + 4) = make_float4(hi[4], hi[5], hi[6], hi[7]);
    }
}

// ---------------------------------------------------------------------------
// 2x2 maxpool, NCHW.
// ---------------------------------------------------------------------------
__global__ void maxpool2x2(const float* __restrict__ in,
                           float* __restrict__ out,
                           int total, int C, int Ho, int Wo)
{
    int idx = blockIdx.x * blockDim.x + threadIdx.x;
    if (idx >= total) return;
    int x = idx % Wo;
    int y = (idx / Wo) % Ho;
    int rest = idx / (Wo * Ho);
    const int Wi = 2 * Wo;
    const float* p = in + ((size_t)rest * (2 * Ho) + 2 * y) * Wi + 2 * x;
    float m = fmaxf(fmaxf(p[0], p[1]), fmaxf(p[Wi], p[Wi + 1]));
    out[idx] = m;
}

// ---------------------------------------------------------------------------
template <int CIN, int COUT, int CHUNK, int TH, int TW, int TPB>
static inline void launch_conv(const float* in, const float* w, const float* b,
                               float* out, int H, int W, int N)
{
    dim3 grid((W / TW) * (H / TH), N, COUT / 64);
    conv3x3_bias_relu<CIN, COUT, CHUNK, TH, TW, TPB>
        <<<grid, TPB>>>(in, w, b, out, H, W);
}

static inline void launch_pool(const float* in, float* out, int N, int C, int Hi, int Wi)
{
    int Ho = Hi / 2, Wo = Wi / 2;
    int total = N * C * Ho * Wo;
    maxpool2x2<<<(total + 255) / 256, 256>>>(in, out, total, C, Ho, Wo);
}

extern "C" void kernel_launch(void* const* d_in, const int* in_sizes, int n_in,
                              void* d_out, int out_size)
{
    (void)in_sizes; (void)n_in; (void)out_size;

    const float* x = (const float*)d_in[0];          // (2,3,384,384)
    const float* w[11];
    const float* b[11];
    for (int k = 1; k <= 10; ++k) {
        w[k] = (const float*)d_in[2 + 2 * (k - 1)];
        b[k] = (const float*)d_in[3 + 2 * (k - 1)];
    }

    float* A;
    float* Bb;
    cudaGetSymbolAddress((void**)&A,  g_bufA);
    cudaGetSymbolAddress((void**)&Bb, g_bufB);
    float* O = (float*)d_out;
    const int N = 2;

    // Stage 1 @ 384x384  (tiles 8x32, 256 thr)
    launch_conv<3,   64, 3, 8, 32, 256>(x,  w[1], b[1], A,  384, 384, N);
    launch_conv<64,  64, 4, 8, 32, 256>(A,  w[2], b[2], Bb, 384, 384, N);
    launch_pool(Bb, A, N, 64, 384, 384);              // -> 192x192

    // Stage 2 @ 192x192
    launch_conv<64, 128, 4, 8, 32, 256>(A,  w[3], b[3], Bb, 192, 192, N);
    launch_conv<128,128, 4, 8, 32, 256>(Bb, w[4], b[4], A,  192, 192, N);
    launch_pool(A, Bb, N, 128, 192, 192);             // -> 96x96

    // Stage 3 @ 96x96
    launch_conv<128,256, 4, 8, 32, 256>(Bb, w[5], b[5], A,  96, 96, N);
    launch_conv<256,256, 4, 8, 32, 256>(A,  w[6], b[6], Bb, 96, 96, N);
    launch_conv<256,256, 4, 8, 32, 256>(Bb, w[7], b[7], A,  96, 96, N);
    launch_pool(A, Bb, N, 256, 96, 96);               // -> 48x48

    // Stage 4 @ 48x48   (tiles 8x16, 128 thr -> 288 CTAs per layer)
    launch_conv<256,512, 4, 8, 16, 128>(Bb, w[8],  b[8],  A,  48, 48, N);
    launch_conv<512,512, 4, 8, 16, 128>(A,  w[9],  b[9],  Bb, 48, 48, N);
    launch_conv<512,512, 4, 8, 16, 128>(Bb, w[10], b[10], O,  48, 48, N);
}

// round 10
// speedup vs baseline: 2.8563x; 2.6042x over previous
#include <cuda_runtime.h>
#include <cuda_bf16.h>
#include <cstdint>

// ---------------------------------------------------------------------------
// APD2Net: graph_conv == 3x3 SAME conv (weights (O,C,9), k=ky*3+kx),
// graph_pool == 2x2 maxpool. NCHW fp32 end-to-end.
//
// R10: conv2..conv10 on the TENSOR pipe via baseline-PTX
// mma.sync.m16n8k8.tf32 (tcgen05 is unavailable: harness PTX targets sm_103,
// not sm_103a). Implicit GEMM, tap-decomposed; B fragments are read straight
// out of ONE padded input tile per cin-chunk (taps = address shifts).
// Activations are tf32-rounded at producer epilogues. conv1 stays FFMA2.
// ---------------------------------------------------------------------------

__device__ float g_bufA[2u * 64u * 384u * 384u];
__device__ float g_bufB[2u * 64u * 384u * 384u];
__device__ float g_bufW[512u * 512u * 9u];       // transformed weights (9,O,C)

__device__ __forceinline__ uint32_t f32_to_tf32(float v) {
    uint32_t t;
    asm("cvt.rna.tf32.f32 %0, %1;" : "=r"(t) : "f"(v));
    return t;
}

// ============================ weight transform =============================
// w: (COUT, CIN, 9) -> wT: (9, COUT, CIN), tf32-rounded
__global__ void transform_w(const float* __restrict__ w, float* __restrict__ wT,
                            int COUT, int CIN)
{
    int idx = blockIdx.x * blockDim.x + threadIdx.x;
    int tot = COUT * CIN * 9;
    if (idx >= tot) return;
    int t = idx % 9;
    int rest = idx / 9;
    int c = rest % CIN;
    int oc = rest / CIN;
    wT[((size_t)t * COUT + oc) * CIN + c] =
        __uint_as_float(f32_to_tf32(w[idx]));
}

// ============================ tensor conv ==================================
// Block 256 thr = 8 warps (warp_m = wid&1 -> 2x32 oc, warp_n = wid>>1 -> 4x32 px)
// CTA tile: 64 oc x 128 px (8y x 16x). K = CIN per tap, chunks of 32.
// Smem: As[9][64][36] (all taps, pitch 36 == 4 mod 32 -> conflict-free A frags)
//       Xs[32][10][20] (padded input tile, pitch 200 == 8 mod 32 -> cf B frags)
template <int CIN, int COUT, bool ROUND>
__global__ void __launch_bounds__(256, 2)
conv3x3_mma(const float* __restrict__ in,
            const float* __restrict__ wT,    // (9, COUT, CIN) tf32 bits
            const float* __restrict__ bias,
            float* __restrict__ out, int H, int W)
{
    constexpr int KC = 32;
    static_assert(CIN % KC == 0, "");
    constexpr int NCH = CIN / KC;
    constexpr int APITCH = 36;                 // floats per A row
    constexpr int ATAP = 64 * APITCH;          // 2304 floats per tap

    extern __shared__ float sm[];
    float* As = sm;                            // 9*2304 = 20736 floats
    float* Xs = sm + 9 * ATAP;                 // 32*10*20 = 6400 floats

    const int tid  = threadIdx.x;
    const int lane = tid & 31;
    const int wid  = tid >> 5;
    const int gid  = lane >> 2;                // 0..7
    const int tig  = lane & 3;                 // 0..3
    const int warp_m = wid & 1;
    const int warp_n = wid >> 1;               // 0..3

    const int tiles_x = W / 16;
    const int bx = (blockIdx.x % tiles_x) * 16;
    const int by = (blockIdx.x / tiles_x) * 8;
    const int n_img = blockIdx.y;
    const int oc_base = blockIdx.z * 64;

    float acc[2][4][4];
    #pragma unroll
    for (int mt = 0; mt < 2; ++mt)
        #pragma unroll
        for (int nt = 0; nt < 4; ++nt)
            #pragma unroll
            for (int r = 0; r < 4; ++r) acc[mt][nt][r] = 0.0f;

    // per-lane B coordinates (per nt): y0, x0+gid
    int b_y0[4], b_x[4];
    #pragma unroll
    for (int nt = 0; nt < 4; ++nt) {
        int n_base = warp_n * 32 + nt * 8;
        b_y0[nt] = n_base >> 4;
        b_x[nt]  = (n_base & 15) + gid;
    }

    #pragma unroll 1
    for (int ch = 0; ch < NCH; ++ch) {
        const int c0 = ch * KC;
        __syncthreads();   // protect As/Xs still in use by other warps

        // ---- stage A: 9 taps x 64 oc x 32 cin (float4, coalesced)
        {
            const float* wbase = wT + (size_t)oc_base * CIN + c0;
            #pragma unroll
            for (int it = 0; it < 18; ++it) {   // 9*64*8 f4 / 256
                int idx = it * 256 + tid;
                int tap = idx >> 9;             // /512
                int r   = idx & 511;
                int m   = r >> 3;
                int k4  = r & 7;
                float4 v = *reinterpret_cast<const float4*>(
                    wbase + ((size_t)tap * COUT + m) * CIN + k4 * 4);
                float* dst = As + tap * ATAP + m * APITCH + k4 * 4;
                dst[0] = v.x; dst[1] = v.y; dst[2] = v.z; dst[3] = v.w;
            }
        }
        // ---- stage X: 32 cin x 10 y x 18 x (zero-pad borders), pitch 20
        {
            constexpr int TOT = 32 * 10 * 18;
            #pragma unroll
            for (int it = 0; it < (TOT + 255) / 256; ++it) {
                int idx = it * 256 + tid;
                if (idx < TOT) {
                    int c  = idx / 180;
                    int r  = idx % 180;
                    int yy = r / 18;
                    int xx = r % 18;
                    int gy = by + yy - 1;
                    int gx = bx + xx - 1;
                    float v = 0.0f;
                    if (gy >= 0 && gy < H && gx >= 0 && gx < W)
                        v = in[(((size_t)n_img * CIN + c0 + c) * H + gy) * W + gx];
                    Xs[c * 200 + yy * 20 + xx] = v;
                }
            }
        }
        __syncthreads();

        // ---- compute: 9 taps x 4 k8-steps x 8 mma
        #pragma unroll 1
        for (int tap = 0; tap < 9; ++tap) {
            const int ky = tap / 3, kx = tap % 3;
            const float* ab = As + tap * ATAP;
            #pragma unroll
            for (int ks = 0; ks < 4; ++ks) {
                uint32_t a[2][4];
                #pragma unroll
                for (int mt = 0; mt < 2; ++mt) {
                    int row = warp_m * 32 + mt * 16 + gid;
                    const float* ap = ab + row * APITCH + ks * 8 + tig;
                    a[mt][0] = __float_as_uint(ap[0]);
                    a[mt][1] = __float_as_uint(ap[8 * APITCH]);
                    a[mt][2] = __float_as_uint(ap[4]);
                    a[mt][3] = __float_as_uint(ap[8 * APITCH + 4]);
                }
                uint32_t b[4][2];
                #pragma unroll
                for (int nt = 0; nt < 4; ++nt) {
                    const float* bp = Xs + (ks * 8 + tig) * 200
                                    + (b_y0[nt] + ky) * 20 + b_x[nt] + kx;
                    b[nt][0] = __float_as_uint(bp[0]);
                    b[nt][1] = __float_as_uint(bp[4 * 200]);
                }
                #pragma unroll
                for (int mt = 0; mt < 2; ++mt)
                    #pragma unroll
                    for (int nt = 0; nt < 4; ++nt) {
                        float* d = acc[mt][nt];
                        asm volatile(
                            "mma.sync.aligned.m16n8k8.row.col.f32.tf32.tf32.f32 "
                            "{%0,%1,%2,%3}, {%4,%5,%6,%7}, {%8,%9}, {%0,%1,%2,%3};"
                            : "+f"(d[0]), "+f"(d[1]), "+f"(d[2]), "+f"(d[3])
                            : "r"(a[mt][0]), "r"(a[mt][1]), "r"(a[mt][2]), "r"(a[mt][3]),
                              "r"(b[nt][0]), "r"(b[nt][1]));
                    }
            }
        }
    }

    // ---- epilogue: bias + relu (+ tf32 round), float2 stores
    #pragma unroll
    for (int mt = 0; mt < 2; ++mt) {
        int oc0 = oc_base + warp_m * 32 + mt * 16 + gid;
        float bv0 = bias[oc0];
        float bv1 = bias[oc0 + 8];
        #pragma unroll
        for (int nt = 0; nt < 4; ++nt) {
            int px = warp_n * 32 + nt * 8 + tig * 2;
            int gy = by + (px >> 4);
            int gx = bx + (px & 15);
            float v00 = fmaxf(acc[mt][nt][0] + bv0, 0.0f);
            float v01 = fmaxf(acc[mt][nt][1] + bv0, 0.0f);
            float v10 = fmaxf(acc[mt][nt][2] + bv1, 0.0f);
            float v11 = fmaxf(acc[mt][nt][3] + bv1, 0.0f);
            if (ROUND) {
                v00 = __uint_as_float(f32_to_tf32(v00));
                v01 = __uint_as_float(f32_to_tf32(v01));
                v10 = __uint_as_float(f32_to_tf32(v10));
                v11 = __uint_as_float(f32_to_tf32(v11));
            }
            float* d0 = out + (((size_t)n_img * COUT + oc0) * H + gy) * W + gx;
            float* d1 = d0 + (size_t)8 * H * W;
            *reinterpret_cast<float2*>(d0) = make_float2(v00, v01);
            *reinterpret_cast<float2*>(d1) = make_float2(v10, v11);
        }
    }
}

// ============================ FFMA2 conv (conv1 only) ======================
__device__ __forceinline__ unsigned long long fma2(unsigned long long a,
                                                   unsigned long long b,
                                                   unsigned long long c) {
    unsigned long long d;
    asm("fma.rn.f32x2 %0, %1, %2, %3;" : "=l"(d) : "l"(a), "l"(b), "l"(c));
    return d;
}
__device__ __forceinline__ unsigned long long dup2(float v) {
    unsigned long long d;
    asm("mov.b64 %0, {%1, %1};" : "=l"(d) : "f"(v));
    return d;
}
__device__ __forceinline__ float2 unpack2(unsigned long long v) {
    float2 r;
    asm("mov.b64 {%0, %1}, %2;" : "=f"(r.x), "=f"(r.y) : "l"(v));
    return r;
}
__device__ __host__ __forceinline__ int woff_of(int ocg) {
    return ocg * 8 + (ocg >> 2) * 2;
}

template <int CIN, int COUT, int CHUNK, int TH, int TW, bool ROUND>
__global__ void __launch_bounds__(256, 2)
conv3x3_ffma(const float* __restrict__ in,
             const float* __restrict__ wgt,
             const float* __restrict__ bias,
             float* __restrict__ out, int H, int W)
{
    constexpr int OCB = 64;
    constexpr int WROW = 68;
    constexpr int IROW = TW + 2;
    constexpr int CG = TW / 8;

    __shared__ __align__(16) float wsm[CHUNK][9][WROW];
    __shared__ float insm[CHUNK][TH + 2][IROW];

    const int tiles_x = W / TW;
    const int bx = (blockIdx.x % tiles_x) * TW;
    const int by = (blockIdx.x / tiles_x) * TH;
    const int n  = blockIdx.y;
    const int oc_base = blockIdx.z * OCB;

    const int tid = threadIdx.x;
    const int ocg = tid & 7;
    const int pg  = tid >> 3;
    const int row = pg / CG;
    const int col = (pg % CG) * 8;
    const int woff = woff_of(ocg);

    unsigned long long acc[4][8];
    #pragma unroll
    for (int op = 0; op < 4; ++op)
        #pragma unroll
        for (int p = 0; p < 8; ++p) acc[op][p] = 0ull;

    #pragma unroll 1
    for (int c0 = 0; c0 < CIN; c0 += CHUNK) {
        {
            const float* wg = wgt + (size_t)oc_base * CIN * 9 + (size_t)c0 * 9;
            constexpr int PER_OC = CHUNK * 9;
            constexpr int TOT = OCB * PER_OC;
            for (int idx = tid; idx < TOT; idx += 256) {
                int oc = idx / PER_OC;
                int r  = idx % PER_OC;
                float v = wg[(size_t)oc * CIN * 9 + r];
                wsm[r / 9][r % 9][woff_of(oc >> 3) + (oc & 7)] = v;
            }
        }
        {
            constexpr int TILE2D = (TH + 2) * IROW;
            constexpr int TOT = CHUNK * TILE2D;
            for (int idx = tid; idx < TOT; idx += 256) {
                int c   = idx / TILE2D;
                int rem = idx % TILE2D;
                int iy  = rem / IROW;
                int ix  = rem % IROW;
                int gy = by + iy - 1;
                int gx = bx + ix - 1;
                float v = 0.0f;
                if (gy >= 0 && gy < H && gx >= 0 && gx < W)
                    v = in[(((size_t)n * CIN + c0 + c) * H + gy) * W + gx];
                insm[c][iy][ix] = v;
            }
        }
        __syncthreads();

        #pragma unroll 1
        for (int c = 0; c < CHUNK; ++c) {
            #pragma unroll
            for (int ky = 0; ky < 3; ++ky) {
                const float* rp = &insm[c][row + ky][col];
                unsigned long long d[10];
                #pragma unroll
                for (int i = 0; i < 10; ++i) d[i] = dup2(rp[i]);
                #pragma unroll
                for (int kx = 0; kx < 3; ++kx) {
                    const float* wp = &wsm[c][ky * 3 + kx][woff];
                    unsigned long long w2[4];
                    #pragma unroll
                    for (int j = 0; j < 4; ++j)
                        w2[j] = *reinterpret_cast<const unsigned long long*>(wp + 2 * j);
                    #pragma unroll
                    for (int op = 0; op < 4; ++op)
                        #pragma unroll
                        for (int p = 0; p < 8; ++p)
                            acc[op][p] = fma2(w2[op], d[kx + p], acc[op][p]);
                }
            }
        }
        __syncthreads();
    }

    const int gy = by + row;
    const int gx = bx + col;
    #pragma unroll
    for (int op = 0; op < 4; ++op) {
        const int oc0 = oc_base + ocg * 8 + 2 * op;
        const float b0 = bias[oc0];
        const float b1 = bias[oc0 + 1];
        float lo[8], hi[8];
        #pragma unroll
        for (int p = 0; p < 8; ++p) {
            float2 u = unpack2(acc[op][p]);
            lo[p] = fmaxf(u.x + b0, 0.0f);
            hi[p] = fmaxf(u.y + b1, 0.0f);
            if (ROUND) {
                lo[p] = __uint_as_float(f32_to_tf32(lo[p]));
                hi[p] = __uint_as_float(f32_to_tf32(hi[p]));
            }
        }
        float* dst0 = out + (((size_t)n * COUT + oc0) * H + gy) * W + gx;
        float* dst1 = dst0 + (size_t)H * W;
        *reinterpret_cast<float4*>(dst0)     = make_float4(lo[0], lo[1], lo[2], lo[3]);
        *reinterpret_cast<float4*>(dst0 + 4) = make_float4(lo[4], lo[5], lo[6], lo[7]);
        *reinterpret_cast<float4*>(dst1)     = make_float4(hi[0], hi[1], hi[2], hi[3]);
        *reinterpret_cast<float4*>(dst1 + 4) = make_float4(hi[4], hi[5], hi[6], hi[7]);
    }
}

// ============================ maxpool ======================================
__global__ void maxpool2x2(const float* __restrict__ in,
                           float* __restrict__ out,
                           int total, int C, int Ho, int Wo)
{
    int idx = blockIdx.x * blockDim.x + threadIdx.x;
    if (idx >= total) return;
    int x = idx % Wo;
    int y = (idx / Wo) % Ho;
    int rest = idx / (Wo * Ho);
    const int Wi = 2 * Wo;
    const float* p = in + ((size_t)rest * (2 * Ho) + 2 * y) * Wi + 2 * x;
    float m = fmaxf(fmaxf(p[0], p[1]), fmaxf(p[Wi], p[Wi + 1]));
    out[idx] = m;
}

// ============================ launchers ====================================
static constexpr int SMEM_MMA = (9 * 64 * 36 + 32 * 10 * 20) * 4;   // 108544 B

template <int CIN, int COUT, bool ROUND>
static inline void launch_tconv(const float* in, const float* w, const float* b,
                                float* out, int H, int W, int N, float* wT)
{
    int tot = COUT * CIN * 9;
    transform_w<<<(tot + 255) / 256, 256>>>(w, wT, COUT, CIN);

    cudaFuncSetAttribute(conv3x3_mma<CIN, COUT, ROUND>,
                         cudaFuncAttributeMaxDynamicSharedMemorySize, SMEM_MMA);
    dim3 grid((W / 16) * (H / 8), N, COUT / 64);
    conv3x3_mma<CIN, COUT, ROUND><<<grid, 256, SMEM_MMA>>>(in, wT, b, out, H, W);
}

static inline void launch_pool(const float* in, float* out, int N, int C, int Hi, int Wi)
{
    int Ho = Hi / 2, Wo = Wi / 2;
    int total = N * C * Ho * Wo;
    maxpool2x2<<<(total + 255) / 256, 256>>>(in, out, total, C, Ho, Wo);
}

extern "C" void kernel_launch(void* const* d_in, const int* in_sizes, int n_in,
                              void* d_out, int out_size)
{
    (void)in_sizes; (void)n_in; (void)out_size;

    const float* x = (const float*)d_in[0];          // (2,3,384,384)
    const float* w[11];
    const float* b[11];
    for (int k = 1; k <= 10; ++k) {
        w[k] = (const float*)d_in[2 + 2 * (k - 1)];
        b[k] = (const float*)d_in[3 + 2 * (k - 1)];
    }

    float* A;
    float* Bb;
    float* Wt;
    cudaGetSymbolAddress((void**)&A,  g_bufA);
    cudaGetSymbolAddress((void**)&Bb, g_bufB);
    cudaGetSymbolAddress((void**)&Wt, g_bufW);
    float* O = (float*)d_out;
    const int N = 2;

    // Stage 1 @ 384x384 — conv1 FFMA (rounds output to tf32), conv2 tensor
    {
        dim3 grid((384 / 32) * (384 / 8), N, 1);
        conv3x3_ffma<3, 64, 3, 8, 32, true><<<grid, 256>>>(x, w[1], b[1], A, 384, 384);
    }
    launch_tconv<64, 64, true>(A, w[2], b[2], Bb, 384, 384, N, Wt);
    launch_pool(Bb, A, N, 64, 384, 384);              // -> 192x192

    // Stage 2 @ 192x192
    launch_tconv<64, 128, true>(A,  w[3], b[3], Bb, 192, 192, N, Wt);
    launch_tconv<128, 128, true>(Bb, w[4], b[4], A, 192, 192, N, Wt);
    launch_pool(A, Bb, N, 128, 192, 192);             // -> 96x96

    // Stage 3 @ 96x96
    launch_tconv<128, 256, true>(Bb, w[5], b[5], A,  96, 96, N, Wt);
    launch_tconv<256, 256, true>(A,  w[6], b[6], Bb, 96, 96, N, Wt);
    launch_tconv<256, 256, true>(Bb, w[7], b[7], A,  96, 96, N, Wt);
    launch_pool(A, Bb, N, 256, 96, 96);               // -> 48x48

    // Stage 4 @ 48x48
    launch_tconv<256, 512, true>(Bb, w[8],  b[8],  A,  48, 48, N, Wt);
    launch_tconv<512, 512, true>(A,  w[9],  b[9],  Bb, 48, 48, N, Wt);
    launch_tconv<512, 512, false>(Bb, w[10], b[10], O,  48, 48, N, Wt);
}

// round 11
// speedup vs baseline: 2.8945x; 1.0134x over previous
#include <cuda_runtime.h>
#include <cuda_bf16.h>
#include <cstdint>

// ---------------------------------------------------------------------------
// APD2Net: graph_conv == 3x3 SAME conv (weights (O,C,9), k=ky*3+kx),
// graph_pool == 2x2 maxpool. NCHW fp32 end-to-end.
//
// R11: tensor-pipe implicit GEMM (mma.sync.m16n8k8.tf32) with cp.async
// 2-stage double buffering (KC=16). All weight transforms fused into one
// kernel at graph start. conv1 (CIN=3) stays FFMA2.
// ---------------------------------------------------------------------------

__device__ float g_bufA[2u * 64u * 384u * 384u];
__device__ float g_bufB[2u * 64u * 384u * 384u];
__device__ float g_bufW[7630848u];               // all transformed weights

__device__ __forceinline__ uint32_t f32_to_tf32(float v) {
    uint32_t t;
    asm("cvt.rna.tf32.f32 %0, %1;" : "=r"(t) : "f"(v));
    return t;
}
__device__ __forceinline__ void cp_async4(void* smem_dst, const void* gptr, int src_bytes) {
    unsigned sa = (unsigned)__cvta_generic_to_shared(smem_dst);
    asm volatile("cp.async.ca.shared.global [%0], [%1], 4, %2;\n"
                 :: "r"(sa), "l"(gptr), "r"(src_bytes));
}
__device__ __forceinline__ void cp_async8(void* smem_dst, const void* gptr) {
    unsigned sa = (unsigned)__cvta_generic_to_shared(smem_dst);
    asm volatile("cp.async.ca.shared.global [%0], [%1], 8;\n"
                 :: "r"(sa), "l"(gptr));
}
__device__ __forceinline__ void cp_commit() { asm volatile("cp.async.commit_group;"); }
__device__ __forceinline__ void cp_wait1()  { asm volatile("cp.async.wait_group 1;"); }
__device__ __forceinline__ void cp_wait0()  { asm volatile("cp.async.wait_group 0;"); }

// ============================ fused weight transform ========================
// For each layer: w (COUT,CIN,9) -> wT (9,COUT,CIN) tf32-rounded, at offset.
struct WXform {
    const float* src[9];
    long start[10];          // prefix offsets into g_bufW (elements)
    int cout[9], cin[9];
};

__global__ void transform_all(WXform p, float* __restrict__ dstbase)
{
    long gid = (long)blockIdx.x * blockDim.x + threadIdx.x;
    if (gid >= p.start[9]) return;
    int l = 0;
    #pragma unroll
    for (int i = 1; i < 9; ++i) if (gid >= p.start[i]) l = i;
    long local = gid - p.start[l];
    int CIN = p.cin[l], COUT = p.cout[l];
    int t = (int)(local % 9);
    long rest = local / 9;
    int c  = (int)(rest % CIN);
    int oc = (int)(rest / CIN);
    float v = p.src[l][local];
    dstbase[p.start[l] + ((long)t * COUT + oc) * CIN + c] =
        __uint_as_float(f32_to_tf32(v));
}

// ============================ tensor conv ==================================
// Block 256 thr = 8 warps (warp_m = wid&1 -> 2x32 oc, warp_n = wid>>1 -> 4x32 px)
// CTA tile: 64 oc x 128 px (8y x 16x). K chunks of 16, double-buffered cp.async.
// As[2][9][64][18]  (pitch 18 == 18 mod 32 -> conflict-free A frags)
// Xs[2][16][10][20] (pitch 200 == 8 mod 32 -> conflict-free B frags)
template <int CIN, int COUT, bool ROUND>
__global__ void __launch_bounds__(256, 2)
conv3x3_mma(const float* __restrict__ in,
            const float* __restrict__ wT,    // (9, COUT, CIN) tf32 bits
            const float* __restrict__ bias,
            float* __restrict__ out, int H, int W)
{
    constexpr int KC = 16;
    static_assert(CIN % KC == 0, "");
    constexpr int NCH = CIN / KC;
    constexpr int APITCH = 18;
    constexpr int ATAP = 64 * APITCH;          // 1152 floats per tap
    constexpr int ASTG = 9 * ATAP;             // 10368 floats per stage
    constexpr int XSTG = KC * 200;             // 3200 floats per stage

    extern __shared__ float sm[];
    float* As = sm;                            // [2][ASTG]
    float* Xs = sm + 2 * ASTG;                 // [2][XSTG]

    const int tid  = threadIdx.x;
    const int lane = tid & 31;
    const int wid  = tid >> 5;
    const int gid  = lane >> 2;
    const int tig  = lane & 3;
    const int warp_m = wid & 1;
    const int warp_n = wid >> 1;

    const int tiles_x = W / 16;
    const int bx = (blockIdx.x % tiles_x) * 16;
    const int by = (blockIdx.x / tiles_x) * 8;
    const int n_img = blockIdx.y;
    const int oc_base = blockIdx.z * 64;

    float acc[2][4][4];
    #pragma unroll
    for (int mt = 0; mt < 2; ++mt)
        #pragma unroll
        for (int nt = 0; nt < 4; ++nt)
            #pragma unroll
            for (int r = 0; r < 4; ++r) acc[mt][nt][r] = 0.0f;

    int b_y0[4], b_x[4];
    #pragma unroll
    for (int nt = 0; nt < 4; ++nt) {
        int n_base = warp_n * 32 + nt * 8;
        b_y0[nt] = n_base >> 4;
        b_x[nt]  = (n_base & 15) + gid;
    }

    const float* wbase = wT + (size_t)oc_base * CIN;

    // ---- async stage of one chunk into buffers [s]
    auto load_chunk = [&](int s, int ch) {
        const int c0 = ch * KC;
        // A: 9 taps x 64 oc x 16 cin as float2 (8B cp.async, coalesced)
        {
            constexpr int TOT2 = 9 * 64 * 8;       // float2 groups = 4608
            float* dst_base = As + s * ASTG;
            #pragma unroll
            for (int it = 0; it < TOT2 / 256; ++it) {
                int idx = it * 256 + tid;
                int tap = idx >> 9;
                int r   = idx & 511;
                int m   = r >> 3;
                int k2  = r & 7;
                cp_async8(dst_base + tap * ATAP + m * APITCH + k2 * 2,
                          wbase + ((size_t)tap * COUT + m) * CIN + c0 + k2 * 2);
            }
        }
        // X: 16 cin x 10 y x 18 x, zero-fill borders via src_size=0
        {
            constexpr int TOT = KC * 10 * 18;      // 2880
            float* dst_base = Xs + s * XSTG;
            #pragma unroll
            for (int it = 0; it < (TOT + 255) / 256; ++it) {
                int idx = it * 256 + tid;
                if (idx < TOT) {
                    int c  = idx / 180;
                    int r  = idx % 180;
                    int yy = r / 18;
                    int xx = r % 18;
                    int gy = by + yy - 1;
                    int gx = bx + xx - 1;
                    bool ok = (gy >= 0 && gy < H && gx >= 0 && gx < W);
                    const float* src = ok
                        ? in + (((size_t)n_img * CIN + c0 + c) * H + gy) * W + gx
                        : in;
                    cp_async4(dst_base + c * 200 + yy * 20 + xx, src, ok ? 4 : 0);
                }
            }
        }
        cp_commit();
    };

    load_chunk(0, 0);

    #pragma unroll 1
    for (int ch = 0; ch < NCH; ++ch) {
        const int s = ch & 1;
        if (ch + 1 < NCH) { load_chunk(s ^ 1, ch + 1); cp_wait1(); }
        else              { cp_wait0(); }
        __syncthreads();

        const float* ab0 = As + s * ASTG;
        const float* xb  = Xs + s * XSTG;

        #pragma unroll 1
        for (int tap = 0; tap < 9; ++tap) {
            const int ky = tap / 3, kx = tap % 3;
            const float* ab = ab0 + tap * ATAP;
            #pragma unroll
            for (int ks = 0; ks < 2; ++ks) {
                uint32_t a[2][4];
                #pragma unroll
                for (int mt = 0; mt < 2; ++mt) {
                    int row = warp_m * 32 + mt * 16 + gid;
                    const float* ap = ab + row * APITCH + ks * 8 + tig;
                    a[mt][0] = __float_as_uint(ap[0]);
                    a[mt][1] = __float_as_uint(ap[8 * APITCH]);
                    a[mt][2] = __float_as_uint(ap[4]);
                    a[mt][3] = __float_as_uint(ap[8 * APITCH + 4]);
                }
                uint32_t b[4][2];
                #pragma unroll
                for (int nt = 0; nt < 4; ++nt) {
                    const float* bp = xb + (ks * 8 + tig) * 200
                                    + (b_y0[nt] + ky) * 20 + b_x[nt] + kx;
                    b[nt][0] = __float_as_uint(bp[0]);
                    b[nt][1] = __float_as_uint(bp[4 * 200]);
                }
                #pragma unroll
                for (int mt = 0; mt < 2; ++mt)
                    #pragma unroll
                    for (int nt = 0; nt < 4; ++nt) {
                        float* d = acc[mt][nt];
                        asm volatile(
                            "mma.sync.aligned.m16n8k8.row.col.f32.tf32.tf32.f32 "
                            "{%0,%1,%2,%3}, {%4,%5,%6,%7}, {%8,%9}, {%0,%1,%2,%3};"
                            : "+f"(d[0]), "+f"(d[1]), "+f"(d[2]), "+f"(d[3])
                            : "r"(a[mt][0]), "r"(a[mt][1]), "r"(a[mt][2]), "r"(a[mt][3]),
                              "r"(b[nt][0]), "r"(b[nt][1]));
                    }
            }
        }
        __syncthreads();
    }

    // ---- epilogue: bias + relu (+ tf32 round), float2 stores
    #pragma unroll
    for (int mt = 0; mt < 2; ++mt) {
        int oc0 = oc_base + warp_m * 32 + mt * 16 + gid;
        float bv0 = bias[oc0];
        float bv1 = bias[oc0 + 8];
        #pragma unroll
        for (int nt = 0; nt < 4; ++nt) {
            int px = warp_n * 32 + nt * 8 + tig * 2;
            int gy = by + (px >> 4);
            int gx = bx + (px & 15);
            float v00 = fmaxf(acc[mt][nt][0] + bv0, 0.0f);
            float v01 = fmaxf(acc[mt][nt][1] + bv0, 0.0f);
            float v10 = fmaxf(acc[mt][nt][2] + bv1, 0.0f);
            float v11 = fmaxf(acc[mt][nt][3] + bv1, 0.0f);
            if (ROUND) {
                v00 = __uint_as_float(f32_to_tf32(v00));
                v01 = __uint_as_float(f32_to_tf32(v01));
                v10 = __uint_as_float(f32_to_tf32(v10));
                v11 = __uint_as_float(f32_to_tf32(v11));
            }
            float* d0 = out + (((size_t)n_img * COUT + oc0) * H + gy) * W + gx;
            float* d1 = d0 + (size_t)8 * H * W;
            *reinterpret_cast<float2*>(d0) = make_float2(v00, v01);
            *reinterpret_cast<float2*>(d1) = make_float2(v10, v11);
        }
    }
}

// ============================ FFMA2 conv (conv1 only) ======================
__device__ __forceinline__ unsigned long long fma2(unsigned long long a,
                                                   unsigned long long b,
                                                   unsigned long long c) {
    unsigned long long d;
    asm("fma.rn.f32x2 %0, %1, %2, %3;" : "=l"(d) : "l"(a), "l"(b), "l"(c));
    return d;
}
__device__ __forceinline__ unsigned long long dup2(float v) {
    unsigned long long d;
    asm("mov.b64 %0, {%1, %1};" : "=l"(d) : "f"(v));
    return d;
}
__device__ __forceinline__ float2 unpack2(unsigned long long v) {
    float2 r;
    asm("mov.b64 {%0, %1}, %2;" : "=f"(r.x), "=f"(r.y) : "l"(v));
    return r;
}
__device__ __host__ __forceinline__ int woff_of(int ocg) {
    return ocg * 8 + (ocg >> 2) * 2;
}

template <int CIN, int COUT, int CHUNK, int TH, int TW, bool ROUND>
__global__ void __launch_bounds__(256, 2)
conv3x3_ffma(const float* __restrict__ in,
             const float* __restrict__ wgt,
             const float* __restrict__ bias,
             float* __restrict__ out, int H, int W)
{
    constexpr int OCB = 64;
    constexpr int WROW = 68;
    constexpr int IROW = TW + 2;
    constexpr int CG = TW / 8;

    __shared__ __align__(16) float wsm[CHUNK][9][WROW];
    __shared__ float insm[CHUNK][TH + 2][IROW];

    const int tiles_x = W / TW;
    const int bx = (blockIdx.x % tiles_x) * TW;
    const int by = (blockIdx.x / tiles_x) * TH;
    const int n  = blockIdx.y;
    const int oc_base = blockIdx.z * OCB;

    const int tid = threadIdx.x;
    const int ocg = tid & 7;
    const int pg  = tid >> 3;
    const int row = pg / CG;
    const int col = (pg % CG) * 8;
    const int woff = woff_of(ocg);

    unsigned long long acc[4][8];
    #pragma unroll
    for (int op = 0; op < 4; ++op)
        #pragma unroll
        for (int p = 0; p < 8; ++p) acc[op][p] = 0ull;

    #pragma unroll 1
    for (int c0 = 0; c0 < CIN; c0 += CHUNK) {
        {
            const float* wg = wgt + (size_t)oc_base * CIN * 9 + (size_t)c0 * 9;
            constexpr int PER_OC = CHUNK * 9;
            constexpr int TOT = OCB * PER_OC;
            for (int idx = tid; idx < TOT; idx += 256) {
                int oc = idx / PER_OC;
                int r  = idx % PER_OC;
                float v = wg[(size_t)oc * CIN * 9 + r];
                wsm[r / 9][r % 9][woff_of(oc >> 3) + (oc & 7)] = v;
            }
        }
        {
            constexpr int TILE2D = (TH + 2) * IROW;
            constexpr int TOT = CHUNK * TILE2D;
            for (int idx = tid; idx < TOT; idx += 256) {
                int c   = idx / TILE2D;
                int rem = idx % TILE2D;
                int iy  = rem / IROW;
                int ix  = rem % IROW;
                int gy = by + iy - 1;
                int gx = bx + ix - 1;
                float v = 0.0f;
                if (gy >= 0 && gy < H && gx >= 0 && gx < W)
                    v = in[(((size_t)n * CIN + c0 + c) * H + gy) * W + gx];
                insm[c][iy][ix] = v;
            }
        }
        __syncthreads();

        #pragma unroll 1
        for (int c = 0; c < CHUNK; ++c) {
            #pragma unroll
            for (int ky = 0; ky < 3; ++ky) {
                const float* rp = &insm[c][row + ky][col];
                unsigned long long d[10];
                #pragma unroll
                for (int i = 0; i < 10; ++i) d[i] = dup2(rp[i]);
                #pragma unroll
                for (int kx = 0; kx < 3; ++kx) {
                    const float* wp = &wsm[c][ky * 3 + kx][woff];
                    unsigned long long w2[4];
                    #pragma unroll
                    for (int j = 0; j < 4; ++j)
                        w2[j] = *reinterpret_cast<const unsigned long long*>(wp + 2 * j);
                    #pragma unroll
                    for (int op = 0; op < 4; ++op)
                        #pragma unroll
                        for (int p = 0; p < 8; ++p)
                            acc[op][p] = fma2(w2[op], d[kx + p], acc[op][p]);
                }
            }
        }
        __syncthreads();
    }

    const int gy = by + row;
    const int gx = bx + col;
    #pragma unroll
    for (int op = 0; op < 4; ++op) {
        const int oc0 = oc_base + ocg * 8 + 2 * op;
        const float b0 = bias[oc0];
        const float b1 = bias[oc0 + 1];
        float lo[8], hi[8];
        #pragma unroll
        for (int p = 0; p < 8; ++p) {
            float2 u = unpack2(acc[op][p]);
            lo[p] = fmaxf(u.x + b0, 0.0f);
            hi[p] = fmaxf(u.y + b1, 0.0f);
            if (ROUND) {
                lo[p] = __uint_as_float(f32_to_tf32(lo[p]));
                hi[p] = __uint_as_float(f32_to_tf32(hi[p]));
            }
        }
        float* dst0 = out + (((size_t)n * COUT + oc0) * H + gy) * W + gx;
        float* dst1 = dst0 + (size_t)H * W;
        *reinterpret_cast<float4*>(dst0)     = make_float4(lo[0], lo[1], lo[2], lo[3]);
        *reinterpret_cast<float4*>(dst0 + 4) = make_float4(lo[4], lo[5], lo[6], lo[7]);
        *reinterpret_cast<float4*>(dst1)     = make_float4(hi[0], hi[1], hi[2], hi[3]);
        *reinterpret_cast<float4*>(dst1 + 4) = make_float4(hi[4], hi[5], hi[6], hi[7]);
    }
}

// ============================ maxpool ======================================
__global__ void maxpool2x2(const float* __restrict__ in,
                           float* __restrict__ out,
                           int total, int C, int Ho, int Wo)
{
    int idx = blockIdx.x * blockDim.x + threadIdx.x;
    if (idx >= total) return;
    int x = idx % Wo;
    int y = (idx / Wo) % Ho;
    int rest = idx / (Wo * Ho);
    const int Wi = 2 * Wo;
    const float* p = in + ((size_t)rest * (2 * Ho) + 2 * y) * Wi + 2 * x;
    float m = fmaxf(fmaxf(p[0], p[1]), fmaxf(p[Wi], p[Wi + 1]));
    out[idx] = m;
}

// ============================ launchers ====================================
static constexpr int SMEM_MMA = (2 * 9 * 64 * 18 + 2 * 16 * 200) * 4; // 108544 B

template <int CIN, int COUT, bool ROUND>
static inline void launch_tconv(const float* in, const float* wT, const float* b,
                                float* out, int H, int W, int N)
{
    cudaFuncSetAttribute(conv3x3_mma<CIN, COUT, ROUND>,
                         cudaFuncAttributeMaxDynamicSharedMemorySize, SMEM_MMA);
    dim3 grid((W / 16) * (H / 8), N, COUT / 64);
    conv3x3_mma<CIN, COUT, ROUND><<<grid, 256, SMEM_MMA>>>(in, wT, b, out, H, W);
}

static inline void launch_pool(const float* in, float* out, int N, int C, int Hi, int Wi)
{
    int Ho = Hi / 2, Wo = Wi / 2;
    int total = N * C * Ho * Wo;
    maxpool2x2<<<(total + 255) / 256, 256>>>(in, out, total, C, Ho, Wo);
}

extern "C" void kernel_launch(void* const* d_in, const int* in_sizes, int n_in,
                              void* d_out, int out_size)
{
    (void)in_sizes; (void)n_in; (void)out_size;

    const float* x = (const float*)d_in[0];          // (2,3,384,384)
    const float* w[11];
    const float* b[11];
    for (int k = 1; k <= 10; ++k) {
        w[k] = (const float*)d_in[2 + 2 * (k - 1)];
        b[k] = (const float*)d_in[3 + 2 * (k - 1)];
    }

    float* A;
    float* Bb;
    float* Wt;
    cudaGetSymbolAddress((void**)&A,  g_bufA);
    cudaGetSymbolAddress((void**)&Bb, g_bufB);
    cudaGetSymbolAddress((void**)&Wt, g_bufW);
    float* O = (float*)d_out;
    const int N = 2;

    // ---- fused transform of conv2..conv10 weights
    static const int CO[9] = {64, 128, 128, 256, 256, 256, 512, 512, 512};
    static const int CI[9] = {64,  64, 128, 128, 256, 256, 256, 512, 512};
    WXform p;
    long off = 0;
    for (int l = 0; l < 9; ++l) {
        p.src[l] = w[l + 2];
        p.cout[l] = CO[l];
        p.cin[l]  = CI[l];
        p.start[l] = off;
        off += (long)CO[l] * CI[l] * 9;
    }
    p.start[9] = off;                                 // 7,630,848
    {
        long blocks = (off + 255) / 256;
        transform_all<<<(unsigned)blocks, 256>>>(p, Wt);
    }

    // Stage 1 @ 384x384 — conv1 FFMA (tf32-rounded output), conv2 tensor
    {
        dim3 grid((384 / 32) * (384 / 8), N, 1);
        conv3x3_ffma<3, 64, 3, 8, 32, true><<<grid, 256>>>(x, w[1], b[1], A, 384, 384);
    }
    launch_tconv<64, 64, true>(A, Wt + p.start[0], b[2], Bb, 384, 384, N);
    launch_pool(Bb, A, N, 64, 384, 384);              // -> 192x192

    // Stage 2 @ 192x192
    launch_tconv<64, 128, true>(A,  Wt + p.start[1], b[3], Bb, 192, 192, N);
    launch_tconv<128, 128, true>(Bb, Wt + p.start[2], b[4], A, 192, 192, N);
    launch_pool(A, Bb, N, 128, 192, 192);             // -> 96x96

    // Stage 3 @ 96x96
    launch_tconv<128, 256, true>(Bb, Wt + p.start[3], b[5], A,  96, 96, N);
    launch_tconv<256, 256, true>(A,  Wt + p.start[4], b[6], Bb, 96, 96, N);
    launch_tconv<256, 256, true>(Bb, Wt + p.start[5], b[7], A,  96, 96, N);
    launch_pool(A, Bb, N, 256, 96, 96);               // -> 48x48

    // Stage 4 @ 48x48
    launch_tconv<256, 512, true>(Bb, Wt + p.start[6], b[8],  A,  48, 48, N);
    launch_tconv<512, 512, true>(A,  Wt + p.start[7], b[9],  Bb, 48, 48, N);
    launch_tconv<512, 512, false>(Bb, Wt + p.start[8], b[10], O,  48, 48, N);
}

// round 12
// speedup vs baseline: 3.5820x; 1.2376x over previous
#include <cuda_runtime.h>
#include <cuda_bf16.h>
#include <cstdint>

// ---------------------------------------------------------------------------
// APD2Net: graph_conv == 3x3 SAME conv (weights (O,C,9), k=ky*3+kx),
// graph_pool == 2x2 maxpool. NCHW fp32 end-to-end.
//
// R12: tensor-pipe implicit GEMM (mma.sync.m16n8k8.tf32).
//  - A (weights) pre-transformed to MMA FRAGMENT-MAJOR layout: staging is a
//    linear coalesced copy, A fragments load as one LDS.128 per thread.
//  - warp tile 32oc x 64px (nt=8): smem wavefronts per MMA 2.0 -> 1.5.
//  - 128-thr blocks (4 warps, 2m x 2n), CTA tile 64oc x 128px, KC=16
//    cp.async double buffering. conv1 (CIN=3) stays FFMA2.
// ---------------------------------------------------------------------------

__device__ float g_bufA[2u * 64u * 384u * 384u];
__device__ float g_bufB[2u * 64u * 384u * 384u];
__device__ float g_bufW[7630848u];               // all transformed weights

__device__ __forceinline__ uint32_t f32_to_tf32(float v) {
    uint32_t t;
    asm("cvt.rna.tf32.f32 %0, %1;" : "=r"(t) : "f"(v));
    return t;
}
__device__ __forceinline__ void cp_async4(void* smem_dst, const void* gptr, int src_bytes) {
    unsigned sa = (unsigned)__cvta_generic_to_shared(smem_dst);
    asm volatile("cp.async.ca.shared.global [%0], [%1], 4, %2;\n"
                 :: "r"(sa), "l"(gptr), "r"(src_bytes));
}
__device__ __forceinline__ void cp_async16(void* smem_dst, const void* gptr) {
    unsigned sa = (unsigned)__cvta_generic_to_shared(smem_dst);
    asm volatile("cp.async.cg.shared.global [%0], [%1], 16;\n"
                 :: "r"(sa), "l"(gptr));
}
__device__ __forceinline__ void cp_commit() { asm volatile("cp.async.commit_group;"); }
__device__ __forceinline__ void cp_wait1()  { asm volatile("cp.async.wait_group 1;"); }
__device__ __forceinline__ void cp_wait0()  { asm volatile("cp.async.wait_group 0;"); }

// ============================ fused weight transform ========================
// Per layer: w (COUT,CIN,9) -> fragment-major (z)(tap)(k8g)(q)(lane)(reg):
//   z   = oc/64 slice, q = 16-row block (0..3), lane = gid*4+tig,
//   reg = mhalf + 2*khalf  -> oc = z*64+q*16+mhalf*8+gid, c = k8g*8+khalf*4+tig
struct WXform {
    const float* src[9];
    long start[10];
    int cout[9], cin[9];
};

__global__ void transform_all(WXform p, float* __restrict__ dstbase)
{
    long gid0 = (long)blockIdx.x * blockDim.x + threadIdx.x;
    if (gid0 >= p.start[9]) return;
    int l = 0;
    #pragma unroll
    for (int i = 1; i < 9; ++i) if (gid0 >= p.start[i]) l = i;
    long i = gid0 - p.start[l];
    const int CIN = p.cin[l];
    const int K8 = CIN / 8;

    int reg  = (int)(i & 3);
    int lane = (int)((i >> 2) & 31);
    int q    = (int)((i >> 7) & 3);
    long r   = i >> 9;                 // (z*9 + t)*K8 + k8g
    int k8g  = (int)(r % K8);
    long zt  = r / K8;
    int t    = (int)(zt % 9);
    int z    = (int)(zt / 9);

    int tig = lane & 3, gidl = lane >> 2;
    int mhalf = reg & 1, khalf = reg >> 1;
    int oc = z * 64 + q * 16 + mhalf * 8 + gidl;
    int c  = k8g * 8 + khalf * 4 + tig;
    float v = p.src[l][((size_t)oc * CIN + c) * 9 + t];
    dstbase[p.start[l] + i] = __uint_as_float(f32_to_tf32(v));
}

// ============================ tensor conv ==================================
// Block 128 thr = 4 warps: warp_m = wid&1 (2 x 32oc), warp_n = wid>>1 (2 x 64px)
// CTA tile: 64 oc x 128 px (8y x 16x). KC=16 double-buffered.
// As[2][9][1024] fragment-major (lin copy), Xs[2][16][10][20] (pitch 200).
template <int CIN, int COUT, bool ROUND>
__global__ void __launch_bounds__(128, 2)
conv3x3_mma(const float* __restrict__ in,
            const float* __restrict__ wT,
            const float* __restrict__ bias,
            float* __restrict__ out, int H, int W)
{
    constexpr int KC = 16;
    static_assert(CIN % KC == 0, "");
    constexpr int NCH = CIN / KC;
    constexpr int K8 = CIN / 8;
    constexpr int ASTG = 9 * 1024;             // floats per stage
    constexpr int XSTG = KC * 200;

    extern __shared__ float sm[];
    float* As = sm;                            // [2][ASTG]
    float* Xs = sm + 2 * ASTG;                 // [2][XSTG]

    const int tid  = threadIdx.x;
    const int lane = tid & 31;
    const int wid  = tid >> 5;
    const int gid  = lane >> 2;
    const int tig  = lane & 3;
    const int warp_m = wid & 1;
    const int warp_n = wid >> 1;               // 0..1

    const int tiles_x = W / 16;
    const int bx = (blockIdx.x % tiles_x) * 16;
    const int by = (blockIdx.x / tiles_x) * 8;
    const int n_img = blockIdx.y;
    const int zsl = blockIdx.z;
    const int oc_base = zsl * 64;

    float acc[2][8][4];
    #pragma unroll
    for (int mt = 0; mt < 2; ++mt)
        #pragma unroll
        for (int nt = 0; nt < 8; ++nt)
            #pragma unroll
            for (int r = 0; r < 4; ++r) acc[mt][nt][r] = 0.0f;

    int b_y0[8], b_x[8];
    #pragma unroll
    for (int nt = 0; nt < 8; ++nt) {
        int n_base = warp_n * 64 + nt * 8;
        b_y0[nt] = n_base >> 4;
        b_x[nt]  = (n_base & 15) + gid;
    }

    // z-slice base of fragment-major weights: 9 * K8 * 512 floats per slice
    const float* wz = wT + (size_t)zsl * 9 * K8 * 512;

    auto load_chunk = [&](int s, int ch) {
        // A: 9 taps x 1024 floats (2 k8g x 4 q x 128), linear per tap
        {
            float* dst = As + s * ASTG;
            #pragma unroll
            for (int it = 0; it < 18; ++it) {      // 9*256 float4 / 128 thr
                int idx = it * 128 + tid;          // float4 index
                int tap = idx >> 8;                // /256
                int f4  = idx & 255;
                cp_async16(dst + tap * 1024 + f4 * 4,
                           wz + ((size_t)tap * K8 + 2 * ch) * 512 + f4 * 4);
            }
        }
        // X: 16 cin x 10 y x 18 x, zero-fill borders
        {
            const int c0 = ch * KC;
            constexpr int TOT = KC * 10 * 18;      // 2880
            float* dst = Xs + s * XSTG;
            #pragma unroll
            for (int it = 0; it < (TOT + 127) / 128; ++it) {
                int idx = it * 128 + tid;
                if (idx < TOT) {
                    int c  = idx / 180;
                    int r  = idx % 180;
                    int yy = r / 18;
                    int xx = r % 18;
                    int gy = by + yy - 1;
                    int gx = bx + xx - 1;
                    bool ok = (gy >= 0 && gy < H && gx >= 0 && gx < W);
                    const float* src = ok
                        ? in + (((size_t)n_img * CIN + c0 + c) * H + gy) * W + gx
                        : in;
                    cp_async4(dst + c * 200 + yy * 20 + xx, src, ok ? 4 : 0);
                }
            }
        }
        cp_commit();
    };

    load_chunk(0, 0);

    #pragma unroll 1
    for (int ch = 0; ch < NCH; ++ch) {
        const int s = ch & 1;
        if (ch + 1 < NCH) { load_chunk(s ^ 1, ch + 1); cp_wait1(); }
        else              { cp_wait0(); }
        __syncthreads();

        const float* ab0 = As + s * ASTG;
        const float* xb  = Xs + s * XSTG;

        #pragma unroll 1
        for (int tap = 0; tap < 9; ++tap) {
            const int ky = tap / 3, kx = tap % 3;
            const float* ab = ab0 + tap * 1024;
            #pragma unroll
            for (int ks = 0; ks < 2; ++ks) {
                uint32_t a[2][4];
                #pragma unroll
                for (int mt = 0; mt < 2; ++mt) {
                    int q = warp_m * 2 + mt;
                    const float4 af = *reinterpret_cast<const float4*>(
                        ab + ks * 512 + q * 128 + lane * 4);
                    a[mt][0] = __float_as_uint(af.x);
                    a[mt][1] = __float_as_uint(af.y);
                    a[mt][2] = __float_as_uint(af.z);
                    a[mt][3] = __float_as_uint(af.w);
                }
                #pragma unroll
                for (int nt = 0; nt < 8; ++nt) {
                    const float* bp = xb + (ks * 8 + tig) * 200
                                    + (b_y0[nt] + ky) * 20 + b_x[nt] + kx;
                    uint32_t b0 = __float_as_uint(bp[0]);
                    uint32_t b1 = __float_as_uint(bp[4 * 200]);
                    #pragma unroll
                    for (int mt = 0; mt < 2; ++mt) {
                        float* d = acc[mt][nt];
                        asm volatile(
                            "mma.sync.aligned.m16n8k8.row.col.f32.tf32.tf32.f32 "
                            "{%0,%1,%2,%3}, {%4,%5,%6,%7}, {%8,%9}, {%0,%1,%2,%3};"
                            : "+f"(d[0]), "+f"(d[1]), "+f"(d[2]), "+f"(d[3])
                            : "r"(a[mt][0]), "r"(a[mt][1]), "r"(a[mt][2]), "r"(a[mt][3]),
                              "r"(b0), "r"(b1));
                    }
                }
            }
        }
        __syncthreads();
    }

    // ---- epilogue: bias + relu (+ tf32 round), float2 stores
    #pragma unroll
    for (int mt = 0; mt < 2; ++mt) {
        int oc0 = oc_base + (warp_m * 2 + mt) * 16 + gid;
        float bv0 = bias[oc0];
        float bv1 = bias[oc0 + 8];
        #pragma unroll
        for (int nt = 0; nt < 8; ++nt) {
            int px = warp_n * 64 + nt * 8 + tig * 2;
            int gy = by + (px >> 4);
            int gx = bx + (px & 15);
            float v00 = fmaxf(acc[mt][nt][0] + bv0, 0.0f);
            float v01 = fmaxf(acc[mt][nt][1] + bv0, 0.0f);
            float v10 = fmaxf(acc[mt][nt][2] + bv1, 0.0f);
            float v11 = fmaxf(acc[mt][nt][3] + bv1, 0.0f);
            if (ROUND) {
                v00 = __uint_as_float(f32_to_tf32(v00));
                v01 = __uint_as_float(f32_to_tf32(v01));
                v10 = __uint_as_float(f32_to_tf32(v10));
                v11 = __uint_as_float(f32_to_tf32(v11));
            }
            float* d0 = out + (((size_t)n_img * COUT + oc0) * H + gy) * W + gx;
            float* d1 = d0 + (size_t)8 * H * W;
            *reinterpret_cast<float2*>(d0) = make_float2(v00, v01);
            *reinterpret_cast<float2*>(d1) = make_float2(v10, v11);
        }
    }
}

// ============================ FFMA2 conv (conv1 only) ======================
__device__ __forceinline__ unsigned long long fma2(unsigned long long a,
                                                   unsigned long long b,
                                                   unsigned long long c) {
    unsigned long long d;
    asm("fma.rn.f32x2 %0, %1, %2, %3;" : "=l"(d) : "l"(a), "l"(b), "l"(c));
    return d;
}
__device__ __forceinline__ unsigned long long dup2(float v) {
    unsigned long long d;
    asm("mov.b64 %0, {%1, %1};" : "=l"(d) : "f"(v));
    return d;
}
__device__ __forceinline__ float2 unpack2(unsigned long long v) {
    float2 r;
    asm("mov.b64 {%0, %1}, %2;" : "=f"(r.x), "=f"(r.y) : "l"(v));
    return r;
}
__device__ __host__ __forceinline__ int woff_of(int ocg) {
    return ocg * 8 + (ocg >> 2) * 2;
}

template <int CIN, int COUT, int CHUNK, int TH, int TW, bool ROUND>
__global__ void __launch_bounds__(256, 2)
conv3x3_ffma(const float* __restrict__ in,
             const float* __restrict__ wgt,
             const float* __restrict__ bias,
             float* __restrict__ out, int H, int W)
{
    constexpr int OCB = 64;
    constexpr int WROW = 68;
    constexpr int IROW = TW + 2;
    constexpr int CG = TW / 8;

    __shared__ __align__(16) float wsm[CHUNK][9][WROW];
    __shared__ float insm[CHUNK][TH + 2][IROW];

    const int tiles_x = W / TW;
    const int bx = (blockIdx.x % tiles_x) * TW;
    const int by = (blockIdx.x / tiles_x) * TH;
    const int n  = blockIdx.y;
    const int oc_base = blockIdx.z * OCB;

    const int tid = threadIdx.x;
    const int ocg = tid & 7;
    const int pg  = tid >> 3;
    const int row = pg / CG;
    const int col = (pg % CG) * 8;
    const int woff = woff_of(ocg);

    unsigned long long acc[4][8];
    #pragma unroll
    for (int op = 0; op < 4; ++op)
        #pragma unroll
        for (int p = 0; p < 8; ++p) acc[op][p] = 0ull;

    #pragma unroll 1
    for (int c0 = 0; c0 < CIN; c0 += CHUNK) {
        {
            const float* wg = wgt + (size_t)oc_base * CIN * 9 + (size_t)c0 * 9;
            constexpr int PER_OC = CHUNK * 9;
            constexpr int TOT = OCB * PER_OC;
            for (int idx = tid; idx < TOT; idx += 256) {
                int oc = idx / PER_OC;
                int r  = idx % PER_OC;
                float v = wg[(size_t)oc * CIN * 9 + r];
                wsm[r / 9][r % 9][woff_of(oc >> 3) + (oc & 7)] = v;
            }
        }
        {
            constexpr int TILE2D = (TH + 2) * IROW;
            constexpr int TOT = CHUNK * TILE2D;
            for (int idx = tid; idx < TOT; idx += 256) {
                int c   = idx / TILE2D;
                int rem = idx % TILE2D;
                int iy  = rem / IROW;
                int ix  = rem % IROW;
                int gy = by + iy - 1;
                int gx = bx + ix - 1;
                float v = 0.0f;
                if (gy >= 0 && gy < H && gx >= 0 && gx < W)
                    v = in[(((size_t)n * CIN + c0 + c) * H + gy) * W + gx];
                insm[c][iy][ix] = v;
            }
        }
        __syncthreads();

        #pragma unroll 1
        for (int c = 0; c < CHUNK; ++c) {
            #pragma unroll
            for (int ky = 0; ky < 3; ++ky) {
                const float* rp = &insm[c][row + ky][col];
                unsigned long long d[10];
                #pragma unroll
                for (int i = 0; i < 10; ++i) d[i] = dup2(rp[i]);
                #pragma unroll
                for (int kx = 0; kx < 3; ++kx) {
                    const float* wp = &wsm[c][ky * 3 + kx][woff];
                    unsigned long long w2[4];
                    #pragma unroll
                    for (int j = 0; j < 4; ++j)
                        w2[j] = *reinterpret_cast<const unsigned long long*>(wp + 2 * j);
                    #pragma unroll
                    for (int op = 0; op < 4; ++op)
                        #pragma unroll
                        for (int p = 0; p < 8; ++p)
                            acc[op][p] = fma2(w2[op], d[kx + p], acc[op][p]);
                }
            }
        }
        __syncthreads();
    }

    const int gy = by + row;
    const int gx = bx + col;
    #pragma unroll
    for (int op = 0; op < 4; ++op) {
        const int oc0 = oc_base + ocg * 8 + 2 * op;
        const float b0 = bias[oc0];
        const float b1 = bias[oc0 + 1];
        float lo[8], hi[8];
        #pragma unroll
        for (int p = 0; p < 8; ++p) {
            float2 u = unpack2(acc[op][p]);
            lo[p] = fmaxf(u.x + b0, 0.0f);
            hi[p] = fmaxf(u.y + b1, 0.0f);
            if (ROUND) {
                lo[p] = __uint_as_float(f32_to_tf32(lo[p]));
                hi[p] = __uint_as_float(f32_to_tf32(hi[p]));
            }
        }
        float* dst0 = out + (((size_t)n * COUT + oc0) * H + gy) * W + gx;
        float* dst1 = dst0 + (size_t)H * W;
        *reinterpret_cast<float4*>(dst0)     = make_float4(lo[0], lo[1], lo[2], lo[3]);
        *reinterpret_cast<float4*>(dst0 + 4) = make_float4(lo[4], lo[5], lo[6], lo[7]);
        *reinterpret_cast<float4*>(dst1)     = make_float4(hi[0], hi[1], hi[2], hi[3]);
        *reinterpret_cast<float4*>(dst1 + 4) = make_float4(hi[4], hi[5], hi[6], hi[7]);
    }
}

// ============================ maxpool ======================================
__global__ void maxpool2x2(const float* __restrict__ in,
                           float* __restrict__ out,
                           int total, int C, int Ho, int Wo)
{
    int idx = blockIdx.x * blockDim.x + threadIdx.x;
    if (idx >= total) return;
    int x = idx % Wo;
    int y = (idx / Wo) % Ho;
    int rest = idx / (Wo * Ho);
    const int Wi = 2 * Wo;
    const float* p = in + ((size_t)rest * (2 * Ho) + 2 * y) * Wi + 2 * x;
    float m = fmaxf(fmaxf(p[0], p[1]), fmaxf(p[Wi], p[Wi + 1]));
    out[idx] = m;
}

// ============================ launchers ====================================
static constexpr int SMEM_MMA = (2 * 9 * 1024 + 2 * 16 * 200) * 4;  // 99328 B

template <int CIN, int COUT, bool ROUND>
static inline void launch_tconv(const float* in, const float* wT, const float* b,
                                float* out, int H, int W, int N)
{
    cudaFuncSetAttribute(conv3x3_mma<CIN, COUT, ROUND>,
                         cudaFuncAttributeMaxDynamicSharedMemorySize, SMEM_MMA);
    dim3 grid((W / 16) * (H / 8), N, COUT / 64);
    conv3x3_mma<CIN, COUT, ROUND><<<grid, 128, SMEM_MMA>>>(in, wT, b, out, H, W);
}

static inline void launch_pool(const float* in, float* out, int N, int C, int Hi, int Wi)
{
    int Ho = Hi / 2, Wo = Wi / 2;
    int total = N * C * Ho * Wo;
    maxpool2x2<<<(total + 255) / 256, 256>>>(in, out, total, C, Ho, Wo);
}

extern "C" void kernel_launch(void* const* d_in, const int* in_sizes, int n_in,
                              void* d_out, int out_size)
{
    (void)in_sizes; (void)n_in; (void)out_size;

    const float* x = (const float*)d_in[0];          // (2,3,384,384)
    const float* w[11];
    const float* b[11];
    for (int k = 1; k <= 10; ++k) {
        w[k] = (const float*)d_in[2 + 2 * (k - 1)];
        b[k] = (const float*)d_in[3 + 2 * (k - 1)];
    }

    float* A;
    float* Bb;
    float* Wt;
    cudaGetSymbolAddress((void**)&A,  g_bufA);
    cudaGetSymbolAddress((void**)&Bb, g_bufB);
    cudaGetSymbolAddress((void**)&Wt, g_bufW);
    float* O = (float*)d_out;
    const int N = 2;

    // ---- fused fragment-major transform of conv2..conv10 weights
    static const int CO[9] = {64, 128, 128, 256, 256, 256, 512, 512, 512};
    static const int CI[9] = {64,  64, 128, 128, 256, 256, 256, 512, 512};
    WXform p;
    long off = 0;
    for (int l = 0; l < 9; ++l) {
        p.src[l] = w[l + 2];
        p.cout[l] = CO[l];
        p.cin[l]  = CI[l];
        p.start[l] = off;
        off += (long)CO[l] * CI[l] * 9;
    }
    p.start[9] = off;
    {
        long blocks = (off + 255) / 256;
        transform_all<<<(unsigned)blocks, 256>>>(p, Wt);
    }

    // Stage 1 @ 384x384
    {
        dim3 grid((384 / 32) * (384 / 8), N, 1);
        conv3x3_ffma<3, 64, 3, 8, 32, true><<<grid, 256>>>(x, w[1], b[1], A, 384, 384);
    }
    launch_tconv<64, 64, true>(A, Wt + p.start[0], b[2], Bb, 384, 384, N);
    launch_pool(Bb, A, N, 64, 384, 384);              // -> 192x192

    // Stage 2 @ 192x192
    launch_tconv<64, 128, true>(A,  Wt + p.start[1], b[3], Bb, 192, 192, N);
    launch_tconv<128, 128, true>(Bb, Wt + p.start[2], b[4], A, 192, 192, N);
    launch_pool(A, Bb, N, 128, 192, 192);             // -> 96x96

    // Stage 3 @ 96x96
    launch_tconv<128, 256, true>(Bb, Wt + p.start[3], b[5], A,  96, 96, N);
    launch_tconv<256, 256, true>(A,  Wt + p.start[4], b[6], Bb, 96, 96, N);
    launch_tconv<256, 256, true>(Bb, Wt + p.start[5], b[7], A,  96, 96, N);
    launch_pool(A, Bb, N, 256, 96, 96);               // -> 48x48

    // Stage 4 @ 48x48
    launch_tconv<256, 512, true>(Bb, Wt + p.start[6], b[8],  A,  48, 48, N);
    launch_tconv<512, 512, true>(A,  Wt + p.start[7], b[9],  Bb, 48, 48, N);
    launch_tconv<512, 512, false>(Bb, Wt + p.start[8], b[10], O,  48, 48, N);
}

// round 13
// speedup vs baseline: 3.8994x; 1.0886x over previous
#include <cuda_runtime.h>
#include <cuda_bf16.h>
#include <cstdint>

// ---------------------------------------------------------------------------
// APD2Net: graph_conv == 3x3 SAME conv (weights (O,C,9), k=ky*3+kx),
// graph_pool == 2x2 maxpool. NCHW fp32 end-to-end.
//
// R13: tensor-pipe implicit GEMM (mma.sync.m16n8k8.tf32).
//  - A fragment-major in gmem (R12, validated).
//  - X staged k-INTERLEAVED: one LDS.128 = B fragments for 4 MMAs.
//  - 2x2 maxpool FUSED into the epilogue of conv2/conv4/conv7.
//  - conv1 (CIN=3) stays FFMA2.
// ---------------------------------------------------------------------------

__device__ float g_bufA[2u * 64u * 384u * 384u];
__device__ float g_bufB[2u * 64u * 384u * 384u];
__device__ float g_bufW[7630848u];               // all transformed weights

__device__ __forceinline__ uint32_t f32_to_tf32(float v) {
    uint32_t t;
    asm("cvt.rna.tf32.f32 %0, %1;" : "=r"(t) : "f"(v));
    return t;
}
__device__ __forceinline__ void cp_async4(void* smem_dst, const void* gptr, int src_bytes) {
    unsigned sa = (unsigned)__cvta_generic_to_shared(smem_dst);
    asm volatile("cp.async.ca.shared.global [%0], [%1], 4, %2;\n"
                 :: "r"(sa), "l"(gptr), "r"(src_bytes));
}
__device__ __forceinline__ void cp_async16(void* smem_dst, const void* gptr) {
    unsigned sa = (unsigned)__cvta_generic_to_shared(smem_dst);
    asm volatile("cp.async.cg.shared.global [%0], [%1], 16;\n"
                 :: "r"(sa), "l"(gptr));
}
__device__ __forceinline__ void cp_commit() { asm volatile("cp.async.commit_group;"); }
__device__ __forceinline__ void cp_wait1()  { asm volatile("cp.async.wait_group 1;"); }
__device__ __forceinline__ void cp_wait0()  { asm volatile("cp.async.wait_group 0;"); }

// ============================ fused weight transform ========================
// Per layer: w (COUT,CIN,9) -> fragment-major (z)(tap)(k8g)(q)(lane)(reg)
struct WXform {
    const float* src[9];
    long start[10];
    int cout[9], cin[9];
};

__global__ void transform_all(WXform p, float* __restrict__ dstbase)
{
    long gid0 = (long)blockIdx.x * blockDim.x + threadIdx.x;
    if (gid0 >= p.start[9]) return;
    int l = 0;
    #pragma unroll
    for (int i = 1; i < 9; ++i) if (gid0 >= p.start[i]) l = i;
    long i = gid0 - p.start[l];
    const int CIN = p.cin[l];
    const int K8 = CIN / 8;

    int reg  = (int)(i & 3);
    int lane = (int)((i >> 2) & 31);
    int q    = (int)((i >> 7) & 3);
    long r   = i >> 9;                 // (z*9 + t)*K8 + k8g
    int k8g  = (int)(r % K8);
    long zt  = r / K8;
    int t    = (int)(zt % 9);
    int z    = (int)(zt / 9);

    int tig = lane & 3, gidl = lane >> 2;
    int mhalf = reg & 1, khalf = reg >> 1;
    int oc = z * 64 + q * 16 + mhalf * 8 + gidl;
    int c  = k8g * 8 + khalf * 4 + tig;
    float v = p.src[l][((size_t)oc * CIN + c) * 9 + t];
    dstbase[p.start[l] + i] = __uint_as_float(f32_to_tf32(v));
}

// ============================ tensor conv ==================================
// Block 128 thr = 4 warps: warp_m = wid&1 (2 x 32oc), warp_n = wid>>1 (2 x 64px)
// CTA tile: 64 oc x 128 px (8y x 16x). KC=16 double-buffered.
// As[2][9][1024] fragment-major. Xs: k-interleaved float4 planes,
//   plane tig (0..3), pitch 202 16B-units, word = {c=tig, tig+4, tig+8, tig+12}.
template <int CIN, int COUT, bool ROUND, bool POOL>
__global__ void __launch_bounds__(128, 2)
conv3x3_mma(const float* __restrict__ in,
            const float* __restrict__ wT,
            const float* __restrict__ bias,
            float* __restrict__ out, int H, int W)
{
    constexpr int KC = 16;
    static_assert(CIN % KC == 0, "");
    constexpr int NCH = CIN / KC;
    constexpr int K8 = CIN / 8;
    constexpr int ASTG = 9 * 1024;             // floats per A stage
    constexpr int XPL = 202;                   // plane pitch in 16B units
    constexpr int XSTG = 4 * XPL * 4;          // floats per X stage (3232)

    extern __shared__ float sm[];
    float* As = sm;                            // [2][ASTG]
    float* Xs = sm + 2 * ASTG;                 // [2][XSTG]

    const int tid  = threadIdx.x;
    const int lane = tid & 31;
    const int wid  = tid >> 5;
    const int gid  = lane >> 2;
    const int tig  = lane & 3;
    const int warp_m = wid & 1;
    const int warp_n = wid >> 1;               // 0..1

    const int tiles_x = W / 16;
    const int bx = (blockIdx.x % tiles_x) * 16;
    const int by = (blockIdx.x / tiles_x) * 8;
    const int n_img = blockIdx.y;
    const int zsl = blockIdx.z;
    const int oc_base = zsl * 64;

    float acc[2][8][4];
    #pragma unroll
    for (int mt = 0; mt < 2; ++mt)
        #pragma unroll
        for (int nt = 0; nt < 8; ++nt)
            #pragma unroll
            for (int r = 0; r < 4; ++r) acc[mt][nt][r] = 0.0f;

    int b_y0[8], b_x[8];
    #pragma unroll
    for (int nt = 0; nt < 8; ++nt) {
        int n_base = warp_n * 64 + nt * 8;
        b_y0[nt] = n_base >> 4;
        b_x[nt]  = (n_base & 15) + gid;
    }

    const float* wz = wT + (size_t)zsl * 9 * K8 * 512;

    auto load_chunk = [&](int s, int ch) {
        // A: 9 taps x 1024 floats, linear per tap (float4 cp.async)
        {
            float* dst = As + s * ASTG;
            #pragma unroll
            for (int it = 0; it < 18; ++it) {
                int idx = it * 128 + tid;
                int tap = idx >> 8;
                int f4  = idx & 255;
                cp_async16(dst + tap * 1024 + f4 * 4,
                           wz + ((size_t)tap * K8 + 2 * ch) * 512 + f4 * 4);
            }
        }
        // X: 16 cin x 10 y x 18 x -> k-interleaved float4 planes
        {
            const int c0 = ch * KC;
            constexpr int TOT = KC * 10 * 18;      // 2880
            float* dst = Xs + s * XSTG;
            #pragma unroll
            for (int it = 0; it < (TOT + 127) / 128; ++it) {
                int idx = it * 128 + tid;
                if (idx < TOT) {
                    int c  = idx / 180;
                    int r  = idx % 180;
                    int yy = r / 18;
                    int xx = r % 18;
                    int ctig = c & 3;
                    int j    = c >> 2;
                    int gy = by + yy - 1;
                    int gx = bx + xx - 1;
                    bool ok = (gy >= 0 && gy < H && gx >= 0 && gx < W);
                    const float* src = ok
                        ? in + (((size_t)n_img * CIN + c0 + c) * H + gy) * W + gx
                        : in;
                    cp_async4(dst + (ctig * XPL + yy * 20 + xx) * 4 + j,
                              src, ok ? 4 : 0);
                }
            }
        }
        cp_commit();
    };

    load_chunk(0, 0);

    #pragma unroll 1
    for (int ch = 0; ch < NCH; ++ch) {
        const int s = ch & 1;
        if (ch + 1 < NCH) { load_chunk(s ^ 1, ch + 1); cp_wait1(); }
        else              { cp_wait0(); }
        __syncthreads();

        const float* ab0 = As + s * ASTG;
        const float4* xb = reinterpret_cast<const float4*>(Xs + s * XSTG)
                         + tig * XPL;

        #pragma unroll 1
        for (int tap = 0; tap < 9; ++tap) {
            const int ky = tap / 3, kx = tap % 3;
            const float* ab = ab0 + tap * 1024;
            // A fragments for both ks, both mt (4 x LDS.128)
            uint32_t a[2][2][4];
            #pragma unroll
            for (int ks = 0; ks < 2; ++ks)
                #pragma unroll
                for (int mt = 0; mt < 2; ++mt) {
                    int q = warp_m * 2 + mt;
                    const float4 af = *reinterpret_cast<const float4*>(
                        ab + ks * 512 + q * 128 + lane * 4);
                    a[ks][mt][0] = __float_as_uint(af.x);
                    a[ks][mt][1] = __float_as_uint(af.y);
                    a[ks][mt][2] = __float_as_uint(af.z);
                    a[ks][mt][3] = __float_as_uint(af.w);
                }
            #pragma unroll
            for (int nt = 0; nt < 8; ++nt) {
                const float4 bf = xb[(b_y0[nt] + ky) * 20 + b_x[nt] + kx];
                uint32_t b00 = __float_as_uint(bf.x);   // ks0 lo
                uint32_t b01 = __float_as_uint(bf.y);   // ks0 hi
                uint32_t b10 = __float_as_uint(bf.z);   // ks1 lo
                uint32_t b11 = __float_as_uint(bf.w);   // ks1 hi
                #pragma unroll
                for (int mt = 0; mt < 2; ++mt) {
                    float* d = acc[mt][nt];
                    asm volatile(
                        "mma.sync.aligned.m16n8k8.row.col.f32.tf32.tf32.f32 "
                        "{%0,%1,%2,%3}, {%4,%5,%6,%7}, {%8,%9}, {%0,%1,%2,%3};"
                        : "+f"(d[0]), "+f"(d[1]), "+f"(d[2]), "+f"(d[3])
                        : "r"(a[0][mt][0]), "r"(a[0][mt][1]),
                          "r"(a[0][mt][2]), "r"(a[0][mt][3]),
                          "r"(b00), "r"(b01));
                    asm volatile(
                        "mma.sync.aligned.m16n8k8.row.col.f32.tf32.tf32.f32 "
                        "{%0,%1,%2,%3}, {%4,%5,%6,%7}, {%8,%9}, {%0,%1,%2,%3};"
                        : "+f"(d[0]), "+f"(d[1]), "+f"(d[2]), "+f"(d[3])
                        : "r"(a[1][mt][0]), "r"(a[1][mt][1]),
                          "r"(a[1][mt][2]), "r"(a[1][mt][3]),
                          "r"(b10), "r"(b11));
                }
            }
        }
        __syncthreads();
    }

    // ---- epilogue
    if (POOL) {
        // fused 2x2 maxpool: relu/pool commute; bias uniform per window.
        const int Ho = H >> 1, Wo = W >> 1;
        #pragma unroll
        for (int mt = 0; mt < 2; ++mt) {
            int oc0 = oc_base + (warp_m * 2 + mt) * 16 + gid;
            float bv0 = bias[oc0];
            float bv1 = bias[oc0 + 8];
            #pragma unroll
            for (int g = 0; g < 4; ++g) {
                int nt  = (g & 1) | ((g & 2) << 1);   // 0,1,4,5
                int ntb = nt + 2;
                float p0 = fmaxf(fmaxf(acc[mt][nt][0],  acc[mt][nt][1]),
                                 fmaxf(acc[mt][ntb][0], acc[mt][ntb][1]));
                float p1 = fmaxf(fmaxf(acc[mt][nt][2],  acc[mt][nt][3]),
                                 fmaxf(acc[mt][ntb][2], acc[mt][ntb][3]));
                p0 = fmaxf(p0 + bv0, 0.0f);
                p1 = fmaxf(p1 + bv1, 0.0f);
                if (ROUND) {
                    p0 = __uint_as_float(f32_to_tf32(p0));
                    p1 = __uint_as_float(f32_to_tf32(p1));
                }
                int px = warp_n * 64 + nt * 8 + tig * 2;
                int oy = (by + (px >> 4)) >> 1;
                int ox = (bx + (px & 15)) >> 1;
                out[(((size_t)n_img * COUT + oc0) * Ho + oy) * Wo + ox] = p0;
                out[(((size_t)n_img * COUT + oc0 + 8) * Ho + oy) * Wo + ox] = p1;
            }
        }
    } else {
        #pragma unroll
        for (int mt = 0; mt < 2; ++mt) {
            int oc0 = oc_base + (warp_m * 2 + mt) * 16 + gid;
            float bv0 = bias[oc0];
            float bv1 = bias[oc0 + 8];
            #pragma unroll
            for (int nt = 0; nt < 8; ++nt) {
                int px = warp_n * 64 + nt * 8 + tig * 2;
                int gy = by + (px >> 4);
                int gx = bx + (px & 15);
                float v00 = fmaxf(acc[mt][nt][0] + bv0, 0.0f);
                float v01 = fmaxf(acc[mt][nt][1] + bv0, 0.0f);
                float v10 = fmaxf(acc[mt][nt][2] + bv1, 0.0f);
                float v11 = fmaxf(acc[mt][nt][3] + bv1, 0.0f);
                if (ROUND) {
                    v00 = __uint_as_float(f32_to_tf32(v00));
                    v01 = __uint_as_float(f32_to_tf32(v01));
                    v10 = __uint_as_float(f32_to_tf32(v10));
                    v11 = __uint_as_float(f32_to_tf32(v11));
                }
                float* d0 = out + (((size_t)n_img * COUT + oc0) * H + gy) * W + gx;
                float* d1 = d0 + (size_t)8 * H * W;
                *reinterpret_cast<float2*>(d0) = make_float2(v00, v01);
                *reinterpret_cast<float2*>(d1) = make_float2(v10, v11);
            }
        }
    }
}

// ============================ FFMA2 conv (conv1 only) ======================
__device__ __forceinline__ unsigned long long fma2(unsigned long long a,
                                                   unsigned long long b,
                                                   unsigned long long c) {
    unsigned long long d;
    asm("fma.rn.f32x2 %0, %1, %2, %3;" : "=l"(d) : "l"(a), "l"(b), "l"(c));
    return d;
}
__device__ __forceinline__ unsigned long long dup2(float v) {
    unsigned long long d;
    asm("mov.b64 %0, {%1, %1};" : "=l"(d) : "f"(v));
    return d;
}
__device__ __forceinline__ float2 unpack2(unsigned long long v) {
    float2 r;
    asm("mov.b64 {%0, %1}, %2;" : "=f"(r.x), "=f"(r.y) : "l"(v));
    return r;
}
__device__ __host__ __forceinline__ int woff_of(int ocg) {
    return ocg * 8 + (ocg >> 2) * 2;
}

template <int CIN, int COUT, int CHUNK, int TH, int TW, bool ROUND>
__global__ void __launch_bounds__(256, 2)
conv3x3_ffma(const float* __restrict__ in,
             const float* __restrict__ wgt,
             const float* __restrict__ bias,
             float* __restrict__ out, int H, int W)
{
    constexpr int OCB = 64;
    constexpr int WROW = 68;
    constexpr int IROW = TW + 2;
    constexpr int CG = TW / 8;

    __shared__ __align__(16) float wsm[CHUNK][9][WROW];
    __shared__ float insm[CHUNK][TH + 2][IROW];

    const int tiles_x = W / TW;
    const int bx = (blockIdx.x % tiles_x) * TW;
    const int by = (blockIdx.x / tiles_x) * TH;
    const int n  = blockIdx.y;
    const int oc_base = blockIdx.z * OCB;

    const int tid = threadIdx.x;
    const int ocg = tid & 7;
    const int pg  = tid >> 3;
    const int row = pg / CG;
    const int col = (pg % CG) * 8;
    const int woff = woff_of(ocg);

    unsigned long long acc[4][8];
    #pragma unroll
    for (int op = 0; op < 4; ++op)
        #pragma unroll
        for (int p = 0; p < 8; ++p) acc[op][p] = 0ull;

    #pragma unroll 1
    for (int c0 = 0; c0 < CIN; c0 += CHUNK) {
        {
            const float* wg = wgt + (size_t)oc_base * CIN * 9 + (size_t)c0 * 9;
            constexpr int PER_OC = CHUNK * 9;
            constexpr int TOT = OCB * PER_OC;
            for (int idx = tid; idx < TOT; idx += 256) {
                int oc = idx / PER_OC;
                int r  = idx % PER_OC;
                float v = wg[(size_t)oc * CIN * 9 + r];
                wsm[r / 9][r % 9][woff_of(oc >> 3) + (oc & 7)] = v;
            }
        }
        {
            constexpr int TILE2D = (TH + 2) * IROW;
            constexpr int TOT = CHUNK * TILE2D;
            for (int idx = tid; idx < TOT; idx += 256) {
                int c   = idx / TILE2D;
                int rem = idx % TILE2D;
                int iy  = rem / IROW;
                int ix  = rem % IROW;
                int gy = by + iy - 1;
                int gx = bx + ix - 1;
                float v = 0.0f;
                if (gy >= 0 && gy < H && gx >= 0 && gx < W)
                    v = in[(((size_t)n * CIN + c0 + c) * H + gy) * W + gx];
                insm[c][iy][ix] = v;
            }
        }
        __syncthreads();

        #pragma unroll 1
        for (int c = 0; c < CHUNK; ++c) {
            #pragma unroll
            for (int ky = 0; ky < 3; ++ky) {
                const float* rp = &insm[c][row + ky][col];
                unsigned long long d[10];
                #pragma unroll
                for (int i = 0; i < 10; ++i) d[i] = dup2(rp[i]);
                #pragma unroll
                for (int kx = 0; kx < 3; ++kx) {
                    const float* wp = &wsm[c][ky * 3 + kx][woff];
                    unsigned long long w2[4];
                    #pragma unroll
                    for (int j = 0; j < 4; ++j)
                        w2[j] = *reinterpret_cast<const unsigned long long*>(wp + 2 * j);
                    #pragma unroll
                    for (int op = 0; op < 4; ++op)
                        #pragma unroll
                        for (int p = 0; p < 8; ++p)
                            acc[op][p] = fma2(w2[op], d[kx + p], acc[op][p]);
                }
            }
        }
        __syncthreads();
    }

    const int gy = by + row;
    const int gx = bx + col;
    #pragma unroll
    for (int op = 0; op < 4; ++op) {
        const int oc0 = oc_base + ocg * 8 + 2 * op;
        const float b0 = bias[oc0];
        const float b1 = bias[oc0 + 1];
        float lo[8], hi[8];
        #pragma unroll
        for (int p = 0; p < 8; ++p) {
            float2 u = unpack2(acc[op][p]);
            lo[p] = fmaxf(u.x + b0, 0.0f);
            hi[p] = fmaxf(u.y + b1, 0.0f);
            if (ROUND) {
                lo[p] = __uint_as_float(f32_to_tf32(lo[p]));
                hi[p] = __uint_as_float(f32_to_tf32(hi[p]));
            }
        }
        float* dst0 = out + (((size_t)n * COUT + oc0) * H + gy) * W + gx;
        float* dst1 = dst0 + (size_t)H * W;
        *reinterpret_cast<float4*>(dst0)     = make_float4(lo[0], lo[1], lo[2], lo[3]);
        *reinterpret_cast<float4*>(dst0 + 4) = make_float4(lo[4], lo[5], lo[6], lo[7]);
        *reinterpret_cast<float4*>(dst1)     = make_float4(hi[0], hi[1], hi[2], hi[3]);
        *reinterpret_cast<float4*>(dst1 + 4) = make_float4(hi[4], hi[5], hi[6], hi[7]);
    }
}

// ============================ launchers ====================================
static constexpr int SMEM_MMA = (2 * 9 * 1024 + 2 * (4 * 202 * 4)) * 4; // 99584 B

template <int CIN, int COUT, bool ROUND, bool POOL>
static inline void launch_tconv(const float* in, const float* wT, const float* b,
                                float* out, int H, int W, int N)
{
    cudaFuncSetAttribute(conv3x3_mma<CIN, COUT, ROUND, POOL>,
                         cudaFuncAttributeMaxDynamicSharedMemorySize, SMEM_MMA);
    dim3 grid((W / 16) * (H / 8), N, COUT / 64);
    conv3x3_mma<CIN, COUT, ROUND, POOL><<<grid, 128, SMEM_MMA>>>(in, wT, b, out, H, W);
}

extern "C" void kernel_launch(void* const* d_in, const int* in_sizes, int n_in,
                              void* d_out, int out_size)
{
    (void)in_sizes; (void)n_in; (void)out_size;

    const float* x = (const float*)d_in[0];          // (2,3,384,384)
    const float* w[11];
    const float* b[11];
    for (int k = 1; k <= 10; ++k) {
        w[k] = (const float*)d_in[2 + 2 * (k - 1)];
        b[k] = (const float*)d_in[3 + 2 * (k - 1)];
    }

    float* A;
    float* Bb;
    float* Wt;
    cudaGetSymbolAddress((void**)&A,  g_bufA);
    cudaGetSymbolAddress((void**)&Bb, g_bufB);
    cudaGetSymbolAddress((void**)&Wt, g_bufW);
    float* O = (float*)d_out;
    const int N = 2;

    // ---- fused fragment-major transform of conv2..conv10 weights
    static const int CO[9] = {64, 128, 128, 256, 256, 256, 512, 512, 512};
    static const int CI[9] = {64,  64, 128, 128, 256, 256, 256, 512, 512};
    WXform p;
    long off = 0;
    for (int l = 0; l < 9; ++l) {
        p.src[l] = w[l + 2];
        p.cout[l] = CO[l];
        p.cin[l]  = CI[l];
        p.start[l] = off;
        off += (long)CO[l] * CI[l] * 9;
    }
    p.start[9] = off;
    {
        long blocks = (off + 255) / 256;
        transform_all<<<(unsigned)blocks, 256>>>(p, Wt);
    }

    // Stage 1 @ 384x384 — conv1 FFMA, conv2 tensor + fused pool -> 192^2
    {
        dim3 grid((384 / 32) * (384 / 8), N, 1);
        conv3x3_ffma<3, 64, 3, 8, 32, true><<<grid, 256>>>(x, w[1], b[1], A, 384, 384);
    }
    launch_tconv<64, 64, true, true>(A, Wt + p.start[0], b[2], Bb, 384, 384, N);

    // Stage 2 @ 192x192 — conv3, conv4 + fused pool -> 96^2
    launch_tconv<64, 128, true, false>(Bb, Wt + p.start[1], b[3], A, 192, 192, N);
    launch_tconv<128, 128, true, true>(A,  Wt + p.start[2], b[4], Bb, 192, 192, N);

    // Stage 3 @ 96x96 — conv5, conv6, conv7 + fused pool -> 48^2
    launch_tconv<128, 256, true, false>(Bb, Wt + p.start[3], b[5], A,  96, 96, N);
    launch_tconv<256, 256, true, false>(A,  Wt + p.start[4], b[6], Bb, 96, 96, N);
    launch_tconv<256, 256, true, true>(Bb,  Wt + p.start[5], b[7], A,  96, 96, N);

    // Stage 4 @ 48x48
    launch_tconv<256, 512, true, false>(A,  Wt + p.start[6], b[8],  Bb, 48, 48, N);
    launch_tconv<512, 512, true, false>(Bb, Wt + p.start[7], b[9],  A,  48, 48, N);
    launch_tconv<512, 512, false, false>(A, Wt + p.start[8], b[10], O,  48, 48, N);
}